// round 14
// baseline (speedup 1.0000x reference)
#include <cuda_runtime.h>
#include <cuda_fp16.h>
#include <math.h>
#include <cstdint>

#define BATCH 300
#define ICH   256
#define OC1   128
#define KPOS  1444
#define ROWS40 1664
#define NCAND 10

// ------------------- device scratch -------------------
// conv1 output (approx), fp16, position-major: [b][row40][oc]
__device__ __align__(16) __half g_xh[(size_t)BATCH * ROWS40 * OC1];
__device__ int   g_cp[BATCH * NCAND];          // candidate positions (top-2 x 5 tiles)
__device__ float g_sc[BATCH * NCAND];          // exact candidate scores
__device__ int   g_sf[BATCH * NCAND];          // exact candidate flat indices
// weight image fp16 hi: [c][oc][64k], k = tap*16 + icL, 128B rows
__device__ __align__(16) unsigned char g_Ah[16 * 16384];
// position-major fp16-hi input: [b][kpos][ic]
__device__ __half g_pH[(size_t)BATCH * KPOS * ICH];

__device__ __forceinline__ uint32_t smem_u32(const void* p) {
    return (uint32_t)__cvta_generic_to_shared(p);
}
__device__ __forceinline__ void ldmx4(uint32_t* r, uint32_t addr) {
    asm volatile("ldmatrix.sync.aligned.m8n8.x4.shared.b16 {%0,%1,%2,%3}, [%4];"
        : "=r"(r[0]), "=r"(r[1]), "=r"(r[2]), "=r"(r[3]) : "r"(addr));
}
__device__ __forceinline__ void mma16816(float* d, const uint32_t* a, const uint32_t* b) {
    asm volatile("mma.sync.aligned.m16n8k16.row.col.f32.f16.f16.f32 "
        "{%0,%1,%2,%3},{%4,%5,%6,%7},{%8,%9},{%0,%1,%2,%3};"
        : "+f"(d[0]), "+f"(d[1]), "+f"(d[2]), "+f"(d[3])
        : "r"(a[0]), "r"(a[1]), "r"(a[2]), "r"(a[3]), "r"(b[0]), "r"(b[1]));
}
__device__ __forceinline__ void cpasync16z(uint32_t dst, const void* src, uint32_t sz) {
    asm volatile("cp.async.cg.shared.global [%0], [%1], 16, %2;"
        :: "r"(dst), "l"(src), "r"(sz));
}
__device__ __forceinline__ bool better(float v, int p, float w, int q) {
    return v > w || (v == w && p < q);
}

// ---------------------------------------------------------------------------
// K0a: W1 -> fp16 hi image [c][oc][64k], k = tap*16 + icL.
// ---------------------------------------------------------------------------
__global__ __launch_bounds__(256) void prep_w_kernel(const float* __restrict__ W1) {
    int p = blockIdx.x * 256 + threadIdx.x;   // 65536 pairs
    int oc = p >> 9;
    int kk = (p & 511) << 1;                  // even k in [0,1024)
    int c = kk >> 6, k2 = kk & 63;
    int tap = k2 >> 4, icL = k2 & 15;
    __half h0 = __float2half(W1[oc * 1024 + (c * 16 + icL) * 4 + tap]);
    __half h1 = __float2half(W1[oc * 1024 + (c * 16 + icL + 1) * 4 + tap]);
    uint32_t uh = ((uint32_t)__half_as_ushort(h1) << 16) | __half_as_ushort(h0);
    *(uint32_t*)(g_Ah + (uint32_t)(c * 16384 + oc * 128 + k2 * 2)) = uh;
}

// ---------------------------------------------------------------------------
// K0b: transpose input: [b][ic][1444] fp32 -> [b][pos][ic] fp16.
// ---------------------------------------------------------------------------
__global__ __launch_bounds__(256) void prep_in_kernel(const float* __restrict__ in) {
    __shared__ float st[32][77];
    const int pt = blockIdx.x, icb = blockIdx.y, b = blockIdx.z;
    const int t = threadIdx.x;
    const float* src = in + ((size_t)(b * ICH + icb * 32) * KPOS) + pt * 76;
    #pragma unroll
    for (int i = 0; i < 10; ++i) {
        int e = t + i * 256;
        if (e < 2432) {
            int icL = e / 76, s = e - icL * 76;
            st[icL][s] = src[(size_t)icL * KPOS + s];
        }
    }
    __syncthreads();
    #pragma unroll
    for (int i = 0; i < 10; ++i) {
        int e = t + i * 256;
        if (e < 2432) {
            int posL = e >> 5, icL = e & 31;
            size_t d = (size_t)(b * KPOS + pt * 76 + posL) * ICH + icb * 32 + icL;
            g_pH[d] = __float2half(st[icL][posL]);
        }
    }
}

// ---------------------------------------------------------------------------
// K1: conv1, tap-decomposed 1-pass fp16 (Ah x Bh), fp32 accum. (frozen)
// ---------------------------------------------------------------------------
#define APITCH 144
#define BPITCH 48
#define OFF_B  18432
#define BUFSZ  35328
#define SMEM_TC (3 * BUFSZ)
#define TPITCH 136

__global__ __launch_bounds__(256, 2) void conv1_tc_kernel(
    const float* __restrict__ bias)
{
    extern __shared__ __align__(16) unsigned char sm[];
    const uint32_t smb = smem_u32(sm);
    const int t = threadIdx.x;
    const int b = blockIdx.x / 13;
    const int tile = blockIdx.x - b * 13;
    const int nbase = tile * 128;

    const int wid = t >> 5, l = t & 31;
    const int wm = wid & 3, wn = wid >> 2;
    const uint32_t aoff = (uint32_t)((wm * 32 + (l & 15)) * APITCH + ((l >> 4) & 1) * 16);
    const uint32_t boff = (uint32_t)((wn * 64 + (l & 7) + ((l >> 4) & 1) * 8) * BPITCH
                                     + ((l >> 3) & 1) * 16);

    float acc[2][8][4];
    #pragma unroll
    for (int mt = 0; mt < 2; ++mt)
        #pragma unroll
        for (int nf = 0; nf < 8; ++nf)
            #pragma unroll
            for (int r = 0; r < 4; ++r) acc[mt][nf][r] = 0.f;

    auto issue = [&](int c) {
        const uint32_t bb = smb + (c % 3) * BUFSZ;
        #pragma unroll
        for (int i = 0; i < 4; ++i) {
            int r = t + i * 256;
            cpasync16z(bb + (r >> 3) * APITCH + (r & 7) * 16,
                       g_Ah + c * 16384 + r * 16, 16);
        }
        #pragma unroll
        for (int i = 0; i < 2; ++i) {
            int e = t + i * 256;
            if (e < 352) {
                int s = e >> 1, half = e & 1;
                int m = nbase - 40 + s;
                int iy = m / 40;
                int px = m - iy * 40;
                bool valid = (m >= 0) && (iy < 38) && (px >= 1) && (px <= 38);
                size_t si = valid ? ((size_t)(b * KPOS + iy * 38 + px - 1) * ICH
                                     + c * 16 + half * 8) : 0;
                cpasync16z(bb + OFF_B + s * BPITCH + half * 16,
                           g_pH + si, valid ? 16u : 0u);
            }
        }
        asm volatile("cp.async.commit_group;" ::: "memory");
    };

    auto compute = [&](int c) {
        const uint32_t bb = smb + (c % 3) * BUFSZ;
        #pragma unroll
        for (int tap = 0; tap < 4; ++tap) {
            const uint32_t koff = tap * 32;
            const int dlt = (tap >> 1) * 40 + (tap & 1);
            uint32_t Ah[2][4], Bh[8][2];
            ldmx4(Ah[0], bb + aoff + koff);
            ldmx4(Ah[1], bb + aoff + 16 * APITCH + koff);
            #pragma unroll
            for (int g = 0; g < 4; ++g) {
                uint32_t r[4];
                ldmx4(r, bb + OFF_B + boff + (dlt + g * 16) * BPITCH);
                Bh[2*g][0] = r[0]; Bh[2*g][1] = r[1];
                Bh[2*g+1][0] = r[2]; Bh[2*g+1][1] = r[3];
            }
            #pragma unroll
            for (int mt = 0; mt < 2; ++mt)
                #pragma unroll
                for (int nf = 0; nf < 8; ++nf)
                    mma16816(acc[mt][nf], Ah[mt], Bh[nf]);
        }
    };

    issue(0);
    issue(1);
    for (int c = 0; c < 16; ++c) {
        if (c == 15) {
            asm volatile("cp.async.wait_group 0;" ::: "memory");
        } else {
            asm volatile("cp.async.wait_group 1;" ::: "memory");
        }
        __syncthreads();
        if (c < 14) issue(c + 2);
        compute(c);
    }
    __syncthreads();

    __half* sT = (__half*)sm;
    float bia[2][2];
    #pragma unroll
    for (int mt = 0; mt < 2; ++mt) {
        int mb = wm * 32 + mt * 16 + (l >> 2);
        bia[mt][0] = __ldg(bias + mb);
        bia[mt][1] = __ldg(bias + mb + 8);
    }
    #pragma unroll
    for (int mt = 0; mt < 2; ++mt)
        #pragma unroll
        for (int nf = 0; nf < 8; ++nf)
            #pragma unroll
            for (int r = 0; r < 4; ++r) {
                int m = wm * 32 + mt * 16 + (l >> 2) + ((r >> 1) ? 8 : 0);
                int n = wn * 64 + nf * 8 + 2 * (l & 3) + (r & 1);
                float v = acc[mt][nf][r] + bia[mt][r >> 1];
                v = v > 0.f ? v : 0.f;
                sT[n * TPITCH + m] = __float2half(v);
            }
    __syncthreads();
    {
        const int row = t >> 1, hf = t & 1;
        const uint4* src = (const uint4*)(sT + row * TPITCH + hf * 64);
        uint4* dst = (uint4*)(g_xh + ((size_t)b * ROWS40 + nbase + row) * OC1 + hf * 64);
        #pragma unroll
        for (int seg = 0; seg < 8; ++seg) dst[seg] = src[seg];
    }
}

// ---------------------------------------------------------------------------
// K2: smem-staged approx diff-conv; top-2 (pos, value) per 8-image-row tile.
// (frozen — measured 70us)
// ---------------------------------------------------------------------------
#define K2_SMEM (360 * 256)

__global__ __launch_bounds__(256) void cls_topk_kernel(
    const float* __restrict__ Wc, const float* __restrict__ bc)
{
    extern __shared__ __align__(16) unsigned char smx[];   // 360 rows x 256B
    __shared__ __align__(16) __half2 swd[16 * 64];         // [tap*4+ch][ocp]
    __shared__ float rv1[256], rv2[256];
    __shared__ int   rp1[256], rp2[256];
    const int tb = blockIdx.x, b = blockIdx.y, t = threadIdx.x;
    const int y0 = tb * 8;
    const int nrows = (38 - y0 < 8) ? 38 - y0 : 8;
    const int npos = nrows * 38;
    const int base40 = y0 * 40;
    const uint32_t smbx = smem_u32(smx);

    #pragma unroll
    for (int i = 0; i < 4; ++i) {
        int e = t + i * 256;
        int combo = e >> 6, ocp = e & 63;
        int tap = combo >> 2, ch = combo & 3;
        int oc0 = ocp * 2;
        float d0 = Wc[(ch + 4) * 512 + oc0 * 4 + tap] - Wc[ch * 512 + oc0 * 4 + tap];
        float d1 = Wc[(ch + 4) * 512 + (oc0 + 1) * 4 + tap]
                 - Wc[ch * 512 + (oc0 + 1) * 4 + tap];
        swd[combo * 64 + ocp] = __floats2half2_rn(d0, d1);
    }

    #pragma unroll
    for (int i = 0; i < 23; ++i) {
        int e = t + i * 256;
        if (e < 5760) {
            int r = e >> 4, q = e & 15;
            cpasync16z(smbx + r * 256 + ((q ^ (r & 15)) << 4),
                       g_xh + ((size_t)b * ROWS40 + base40 + r) * OC1 + q * 8, 16);
        }
    }
    asm volatile("cp.async.commit_group;" ::: "memory");
    asm volatile("cp.async.wait_group 0;" ::: "memory");
    __syncthreads();

    float bd[4];
    #pragma unroll
    for (int a = 0; a < 4; ++a) bd[a] = bc[a + 4] - bc[a];

    float v1 = -1e30f, v2 = -1e30f;
    int p1 = 0x7fffffff, p2 = 0x7fffffff;
    #pragma unroll
    for (int it = 0; it < 2; ++it) {
        int pl = t + it * 256;
        if (pl < npos) {
            int iy = pl / 38, ix = pl - iy * 38;
            int r0 = iy * 40 + ix;
            int rb[4] = {r0, r0 + 1, r0 + 40, r0 + 41};
            float facc[4] = {0.f, 0.f, 0.f, 0.f};
            #pragma unroll
            for (int qb = 0; qb < 4; ++qb) {
                __half2 hacc[4];
                #pragma unroll
                for (int ch = 0; ch < 4; ++ch) hacc[ch] = __float2half2_rn(0.f);
                #pragma unroll
                for (int u = 0; u < 4; ++u) {
                    int q = qb * 4 + u;
                    __half2 xr[4][4];
                    #pragma unroll
                    for (int tap = 0; tap < 4; ++tap)
                        *(uint4*)xr[tap] = *(const uint4*)(smx + rb[tap] * 256
                                            + ((q ^ (rb[tap] & 15)) << 4));
                    #pragma unroll
                    for (int ch = 0; ch < 4; ++ch) {
                        #pragma unroll
                        for (int tap = 0; tap < 4; ++tap) {
                            uint4 wv = *(const uint4*)&swd[(tap * 4 + ch) * 64 + q * 4];
                            __half2* wh = (__half2*)&wv;
                            #pragma unroll
                            for (int k = 0; k < 4; ++k)
                                hacc[ch] = __hfma2(xr[tap][k], wh[k], hacc[ch]);
                        }
                    }
                }
                #pragma unroll
                for (int ch = 0; ch < 4; ++ch) {
                    float2 f = __half22float2(hacc[ch]);
                    facc[ch] += f.x + f.y;
                }
            }
            float pv = facc[0] + bd[0];
            #pragma unroll
            for (int ch = 1; ch < 4; ++ch) {
                float v = facc[ch] + bd[ch];
                if (v > pv) pv = v;
            }
            int p = (y0 + iy) * 38 + ix;
            if (better(pv, p, v1, p1)) { v2 = v1; p2 = p1; v1 = pv; p1 = p; }
            else if (better(pv, p, v2, p2)) { v2 = pv; p2 = p; }
        }
    }
    rv1[t] = v1; rp1[t] = p1; rv2[t] = v2; rp2[t] = p2;
    __syncthreads();
    for (int s = 128; s > 0; s >>= 1) {
        if (t < s) {
            float a1 = rv1[t], a2 = rv2[t];
            int   e1 = rp1[t], e2 = rp2[t];
            float w1 = rv1[t + s], w2 = rv2[t + s];
            int   q1 = rp1[t + s], q2 = rp2[t + s];
            float n1, n2; int m1, m2;
            if (better(a1, e1, w1, q1)) {
                n1 = a1; m1 = e1;
                if (better(w1, q1, a2, e2)) { n2 = w1; m2 = q1; }
                else                        { n2 = a2; m2 = e2; }
            } else {
                n1 = w1; m1 = q1;
                if (better(a1, e1, w2, q2)) { n2 = a1; m2 = e1; }
                else                        { n2 = w2; m2 = q2; }
            }
            rv1[t] = n1; rp1[t] = m1; rv2[t] = n2; rp2[t] = m2;
        }
        __syncthreads();
    }
    if (t == 0) {
        g_cp[b * NCAND + tb * 2]     = rp1[0];
        g_cp[b * NCAND + tb * 2 + 1] = rp2[0];
    }
}

// ---------------------------------------------------------------------------
// K3a: exact score of ONE candidate per block. grid (NCAND, BATCH).
// 256 threads: half = t>>7 (ic half), oc = t&127.
// ---------------------------------------------------------------------------
__global__ __launch_bounds__(256) void score_kernel(
    const float* __restrict__ in, const float* __restrict__ W1,
    const float* __restrict__ b1,
    const float* __restrict__ Wc, const float* __restrict__ bc)
{
    __shared__ float sfeat[2304];
    __shared__ float sxa[512];
    __shared__ float red[4][128];
    const int cand = blockIdx.x, b = blockIdx.y, t = threadIdx.x;
    const int half = t >> 7, oc = t & 127;
    const int pos = g_cp[b * NCAND + cand];
    const int hp = pos / 38, wp = pos % 38;

    #pragma unroll
    for (int i = 0; i < 9; ++i) {
        int e = t + i * 256;
        if (e < 2304) {
            int ic = e / 9, p = e - ic * 9;
            int rr = hp - 1 + p / 3, cc = wp - 1 + p % 3;
            sfeat[e] = (rr >= 0 && rr < 38 && cc >= 0 && cc < 38)
                     ? in[((size_t)(b * ICH + ic) * 38 + rr) * 38 + cc] : 0.f;
        }
    }
    __syncthreads();

    const float4* wr = (const float4*)(W1 + oc * 1024) + half * 128;
    float xw[4] = {0.f, 0.f, 0.f, 0.f};
    for (int icl = 0; icl < 128; ++icl) {
        float4 w = wr[icl];
        int ic = half * 128 + icl;
        const float* sf = &sfeat[ic * 9];
        float s0 = sf[0], s1 = sf[1], s2 = sf[2];
        float s3 = sf[3], s4 = sf[4], s5 = sf[5];
        float s6 = sf[6], s7 = sf[7], s8 = sf[8];
        xw[0] += w.x * s0 + w.y * s1 + w.z * s3 + w.w * s4;
        xw[1] += w.x * s1 + w.y * s2 + w.z * s4 + w.w * s5;
        xw[2] += w.x * s3 + w.y * s4 + w.z * s6 + w.w * s7;
        xw[3] += w.x * s4 + w.y * s5 + w.z * s7 + w.w * s8;
    }
    if (half == 0)
        #pragma unroll
        for (int j = 0; j < 4; ++j) sxa[oc * 4 + j] = xw[j];
    __syncthreads();
    if (half == 1)
        #pragma unroll
        for (int j = 0; j < 4; ++j) sxa[oc * 4 + j] += xw[j];
    __syncthreads();

    if (half == 0) {
        float bv1 = b1[oc];
        float x0 = fmaxf(sxa[oc * 4 + 0] + bv1, 0.f);
        float x1 = fmaxf(sxa[oc * 4 + 1] + bv1, 0.f);
        float x2 = fmaxf(sxa[oc * 4 + 2] + bv1, 0.f);
        float x3 = fmaxf(sxa[oc * 4 + 3] + bv1, 0.f);
        #pragma unroll
        for (int ch = 0; ch < 4; ++ch) {
            float w0 = Wc[(ch + 4) * 512 + oc * 4 + 0] - Wc[ch * 512 + oc * 4 + 0];
            float w1 = Wc[(ch + 4) * 512 + oc * 4 + 1] - Wc[ch * 512 + oc * 4 + 1];
            float w2 = Wc[(ch + 4) * 512 + oc * 4 + 2] - Wc[ch * 512 + oc * 4 + 2];
            float w3 = Wc[(ch + 4) * 512 + oc * 4 + 3] - Wc[ch * 512 + oc * 4 + 3];
            red[ch][oc] = w0 * x0 + w1 * x1 + w2 * x2 + w3 * x3;
        }
    }
    __syncthreads();
    if (t < 4) {
        float s = 0.f;
        #pragma unroll 8
        for (int k = 0; k < 128; ++k) s += red[t][k];
        red[t][0] = s + bc[t + 4] - bc[t];
    }
    __syncthreads();
    if (t == 0) {
        float bv = -1e30f; int bf = 0x7fffffff;
        #pragma unroll
        for (int ch = 0; ch < 4; ++ch) {
            float v = red[ch][0];
            int f = ch * KPOS + pos;
            if (v > bv || (v == bv && f < bf)) { bv = v; bf = f; }
        }
        g_sc[b * NCAND + cand] = bv;
        g_sf[b * NCAND + cand] = bf;
    }
}

// ---------------------------------------------------------------------------
// K3b: pick exact winner of the 10, recompute x there, deltas conv + box.
// ---------------------------------------------------------------------------
__global__ __launch_bounds__(256) void box_kernel(
    const float* __restrict__ in, const float* __restrict__ W1,
    const float* __restrict__ b1,
    const float* __restrict__ Wb, const float* __restrict__ bb,
    const float* __restrict__ anchors, const float* __restrict__ im_info,
    float* __restrict__ out)
{
    __shared__ float sfeat[2304];
    __shared__ float sxa[512];
    __shared__ float red[4][128];
    __shared__ float sBestV;
    __shared__ int   sBestF;

    const int b = blockIdx.x, t = threadIdx.x;
    const int half = t >> 7, oc = t & 127;

    if (t == 0) {
        float bv = -1e30f; int bf = 0x7fffffff;
        #pragma unroll
        for (int j = 0; j < NCAND; ++j) {
            float v = g_sc[b * NCAND + j];
            int f = g_sf[b * NCAND + j];
            if (v > bv || (v == bv && f < bf)) { bv = v; bf = f; }
        }
        sBestV = bv; sBestF = bf;
    }
    __syncthreads();

    const int f = sBestF;
    const int kp = f >> 2, ap = f & 3;
    const int hp = kp / 38, wp = kp % 38;
    #pragma unroll
    for (int i = 0; i < 9; ++i) {
        int e = t + i * 256;
        if (e < 2304) {
            int ic = e / 9, p = e - ic * 9;
            int rr = hp - 1 + p / 3, cc = wp - 1 + p % 3;
            sfeat[e] = (rr >= 0 && rr < 38 && cc >= 0 && cc < 38)
                     ? in[((size_t)(b * ICH + ic) * 38 + rr) * 38 + cc] : 0.f;
        }
    }
    __syncthreads();

    const float4* wr = (const float4*)(W1 + oc * 1024) + half * 128;
    float xw[4] = {0.f, 0.f, 0.f, 0.f};
    for (int icl = 0; icl < 128; ++icl) {
        float4 w = wr[icl];
        int ic = half * 128 + icl;
        const float* sf = &sfeat[ic * 9];
        float s0 = sf[0], s1 = sf[1], s2 = sf[2];
        float s3 = sf[3], s4 = sf[4], s5 = sf[5];
        float s6 = sf[6], s7 = sf[7], s8 = sf[8];
        xw[0] += w.x * s0 + w.y * s1 + w.z * s3 + w.w * s4;
        xw[1] += w.x * s1 + w.y * s2 + w.z * s4 + w.w * s5;
        xw[2] += w.x * s3 + w.y * s4 + w.z * s6 + w.w * s7;
        xw[3] += w.x * s4 + w.y * s5 + w.z * s7 + w.w * s8;
    }
    if (half == 0)
        #pragma unroll
        for (int j = 0; j < 4; ++j) sxa[oc * 4 + j] = xw[j];
    __syncthreads();
    if (half == 1)
        #pragma unroll
        for (int j = 0; j < 4; ++j) sxa[oc * 4 + j] += xw[j];
    __syncthreads();

    if (half == 0) {
        float bv1 = b1[oc];
        float x0 = fmaxf(sxa[oc * 4 + 0] + bv1, 0.f);
        float x1 = fmaxf(sxa[oc * 4 + 1] + bv1, 0.f);
        float x2 = fmaxf(sxa[oc * 4 + 2] + bv1, 0.f);
        float x3 = fmaxf(sxa[oc * 4 + 3] + bv1, 0.f);
        #pragma unroll
        for (int j = 0; j < 4; ++j) {
            const float* wq = Wb + (ap * 4 + j) * 512 + oc * 4;
            red[j][oc] = x0 * wq[0] + x1 * wq[1] + x2 * wq[2] + x3 * wq[3];
        }
    }
    __syncthreads();
    if (t < 4) {
        float s = 0.f;
        #pragma unroll 8
        for (int k = 0; k < 128; ++k) s += red[t][k];
        s += bb[ap * 4 + t];
        float shift = (t & 1) ? hp * 16.f : wp * 16.f;
        float scv = im_info[0];
        float box = (anchors[ap * 4 + t] + shift + s) * scv;
        out[b * 9 + t]     = truncf(box / scv);
        out[b * 9 + 4 + t] = box;
    }
    if (t == 4) out[b * 9 + 8] = 1.f / (1.f + expf(-sBestV));
}

// ---------------------------------------------------------------------------
// K4: proposal loss.
// ---------------------------------------------------------------------------
__global__ void loss_kernel(const float* __restrict__ gt,
                            const int* __restrict__ central,
                            float* __restrict__ out, int out_size)
{
    int idx = central[0];
    bool valid = idx < BATCH;
    int ix = idx < 0 ? 0 : (idx > BATCH - 1 ? BATCH - 1 : idx);
    float vb0 = out[ix * 9 + 4], vb1 = out[ix * 9 + 5];
    float vb2 = out[ix * 9 + 6], vb3 = out[ix * 9 + 7];
    float vs  = out[ix * 9 + 8];
    float xi1 = fmaxf(gt[0], vb0);
    float yi1 = fmaxf(gt[1], vb1);
    float xi2 = fmaxf(gt[2], vb2);
    float yi2 = fmaxf(gt[3], vb3);
    float inter = (xi2 - xi1) * (yi2 - yi1);
    float a1 = (gt[2] - gt[0]) * (gt[3] - gt[1]);
    float a2 = (vb2 - vb0) * (vb3 - vb1);
    float iou = inter / (a1 + a2 - inter);
    float lv = (iou > 0.7f) ? -logf(vs + 1e-5f) : -logf(1.f - vs + 1e-5f);
    out[out_size - 1] = valid ? lv : 0.f;
}

// ---------------------------------------------------------------------------
extern "C" void kernel_launch(void* const* d_in, const int* in_sizes, int n_in,
                              void* d_out, int out_size)
{
    const float* base_feat = (const float*)d_in[0];
    const int*   central   = (const int*)  d_in[1];
    const float* im_info   = (const float*)d_in[2];
    const float* gt_boxes  = (const float*)d_in[3];
    const float* W1        = (const float*)d_in[4];
    const float* b1        = (const float*)d_in[5];
    const float* Wc        = (const float*)d_in[6];
    const float* bc        = (const float*)d_in[7];
    const float* Wb        = (const float*)d_in[8];
    const float* bb        = (const float*)d_in[9];
    const float* anchors   = (const float*)d_in[10];
    float* out = (float*)d_out;

    cudaFuncSetAttribute(conv1_tc_kernel,
                         cudaFuncAttributeMaxDynamicSharedMemorySize, SMEM_TC);
    cudaFuncSetAttribute(cls_topk_kernel,
                         cudaFuncAttributeMaxDynamicSharedMemorySize, K2_SMEM);

    prep_w_kernel<<<256, 256>>>(W1);
    prep_in_kernel<<<dim3(19, 8, BATCH), 256>>>(base_feat);
    conv1_tc_kernel<<<BATCH * 13, 256, SMEM_TC>>>(b1);
    cls_topk_kernel<<<dim3(5, BATCH), 256, K2_SMEM>>>(Wc, bc);
    score_kernel<<<dim3(NCAND, BATCH), 256>>>(base_feat, W1, b1, Wc, bc);
    box_kernel<<<BATCH, 256>>>(base_feat, W1, b1, Wb, bb, anchors, im_info, out);
    loss_kernel<<<1, 1>>>(gt_boxes, central, out, out_size);
}

// round 15
// speedup vs baseline: 1.3526x; 1.3526x over previous
#include <cuda_runtime.h>
#include <cuda_fp16.h>
#include <math.h>
#include <cstdint>

#define BATCH 300
#define ICH   256
#define OC1   128
#define KPOS  1444
#define ROWS40 1664
#define NCAND 10

// ------------------- device scratch -------------------
__device__ __align__(16) __half g_xh[(size_t)BATCH * ROWS40 * OC1];
__device__ int g_cp[BATCH * NCAND];            // candidate positions (top-2 x 5 tiles)
__device__ __align__(16) unsigned char g_Ah[16 * 16384];
__device__ __half g_pH[(size_t)BATCH * KPOS * ICH];

__device__ __forceinline__ uint32_t smem_u32(const void* p) {
    return (uint32_t)__cvta_generic_to_shared(p);
}
__device__ __forceinline__ void ldmx4(uint32_t* r, uint32_t addr) {
    asm volatile("ldmatrix.sync.aligned.m8n8.x4.shared.b16 {%0,%1,%2,%3}, [%4];"
        : "=r"(r[0]), "=r"(r[1]), "=r"(r[2]), "=r"(r[3]) : "r"(addr));
}
__device__ __forceinline__ void mma16816(float* d, const uint32_t* a, const uint32_t* b) {
    asm volatile("mma.sync.aligned.m16n8k16.row.col.f32.f16.f16.f32 "
        "{%0,%1,%2,%3},{%4,%5,%6,%7},{%8,%9},{%0,%1,%2,%3};"
        : "+f"(d[0]), "+f"(d[1]), "+f"(d[2]), "+f"(d[3])
        : "r"(a[0]), "r"(a[1]), "r"(a[2]), "r"(a[3]), "r"(b[0]), "r"(b[1]));
}
__device__ __forceinline__ void cpasync16z(uint32_t dst, const void* src, uint32_t sz) {
    asm volatile("cp.async.cg.shared.global [%0], [%1], 16, %2;"
        :: "r"(dst), "l"(src), "r"(sz));
}
__device__ __forceinline__ bool better(float v, int p, float w, int q) {
    return v > w || (v == w && p < q);
}

// ---------------------------------------------------------------------------
// K0a: W1 -> fp16 hi image [c][oc][64k], k = tap*16 + icL.
// ---------------------------------------------------------------------------
__global__ __launch_bounds__(256) void prep_w_kernel(const float* __restrict__ W1) {
    int p = blockIdx.x * 256 + threadIdx.x;
    int oc = p >> 9;
    int kk = (p & 511) << 1;
    int c = kk >> 6, k2 = kk & 63;
    int tap = k2 >> 4, icL = k2 & 15;
    __half h0 = __float2half(W1[oc * 1024 + (c * 16 + icL) * 4 + tap]);
    __half h1 = __float2half(W1[oc * 1024 + (c * 16 + icL + 1) * 4 + tap]);
    uint32_t uh = ((uint32_t)__half_as_ushort(h1) << 16) | __half_as_ushort(h0);
    *(uint32_t*)(g_Ah + (uint32_t)(c * 16384 + oc * 128 + k2 * 2)) = uh;
}

// ---------------------------------------------------------------------------
// K0b: transpose input: [b][ic][1444] fp32 -> [b][pos][ic] fp16.
// ---------------------------------------------------------------------------
__global__ __launch_bounds__(256) void prep_in_kernel(const float* __restrict__ in) {
    __shared__ float st[32][77];
    const int pt = blockIdx.x, icb = blockIdx.y, b = blockIdx.z;
    const int t = threadIdx.x;
    const float* src = in + ((size_t)(b * ICH + icb * 32) * KPOS) + pt * 76;
    #pragma unroll
    for (int i = 0; i < 10; ++i) {
        int e = t + i * 256;
        if (e < 2432) {
            int icL = e / 76, s = e - icL * 76;
            st[icL][s] = src[(size_t)icL * KPOS + s];
        }
    }
    __syncthreads();
    #pragma unroll
    for (int i = 0; i < 10; ++i) {
        int e = t + i * 256;
        if (e < 2432) {
            int posL = e >> 5, icL = e & 31;
            size_t d = (size_t)(b * KPOS + pt * 76 + posL) * ICH + icb * 32 + icL;
            g_pH[d] = __float2half(st[icL][posL]);
        }
    }
}

// ---------------------------------------------------------------------------
// K1: conv1, tap-decomposed 1-pass fp16. Copy addressing HOISTED out of the
// chunk loop: per-thread src/dst/size descriptors computed once.
// ---------------------------------------------------------------------------
#define APITCH 144
#define BPITCH 48
#define OFF_B  18432
#define BUFSZ  35328
#define SMEM_TC (3 * BUFSZ)
#define TPITCH 136

__global__ __launch_bounds__(256, 2) void conv1_tc_kernel(
    const float* __restrict__ bias)
{
    extern __shared__ __align__(16) unsigned char sm[];
    const uint32_t smb = smem_u32(sm);
    const int t = threadIdx.x;
    const int b = blockIdx.x / 13;
    const int tile = blockIdx.x - b * 13;
    const int nbase = tile * 128;

    const int wid = t >> 5, l = t & 31;
    const int wm = wid & 3, wn = wid >> 2;
    const uint32_t aoff = (uint32_t)((wm * 32 + (l & 15)) * APITCH + ((l >> 4) & 1) * 16);
    const uint32_t boff = (uint32_t)((wn * 64 + (l & 7) + ((l >> 4) & 1) * 8) * BPITCH
                                     + ((l >> 3) & 1) * 16);

    // ---- hoisted copy descriptors ----
    const uint32_t adst0 = (uint32_t)((t >> 3) * APITCH + (t & 7) * 16);
    const unsigned char* asrc0 = g_Ah + t * 16;
    const unsigned char* bsrc0;
    const unsigned char* bsrc1 = nullptr;
    uint32_t bdst0, bdst1 = 0, bsz0, bsz1 = 0;
    {
        int e = t;                               // entry 0 (all threads)
        int s = e >> 1, half = e & 1;
        int m = nbase - 40 + s;
        int iy = m / 40, px = m - iy * 40;
        bool valid = (m >= 0) && (iy < 38) && (px >= 1) && (px <= 38);
        size_t si = valid ? ((size_t)(b * KPOS + iy * 38 + px - 1) * ICH + half * 8) : 0;
        bsrc0 = (const unsigned char*)(g_pH + si);
        bdst0 = (uint32_t)(OFF_B + s * BPITCH + half * 16);
        bsz0 = valid ? 16u : 0u;
    }
    if (t < 96) {
        int e = t + 256;                         // entry 1 (t < 96)
        int s = e >> 1, half = e & 1;
        int m = nbase - 40 + s;
        int iy = m / 40, px = m - iy * 40;
        bool valid = (m >= 0) && (iy < 38) && (px >= 1) && (px <= 38);
        size_t si = valid ? ((size_t)(b * KPOS + iy * 38 + px - 1) * ICH + half * 8) : 0;
        bsrc1 = (const unsigned char*)(g_pH + si);
        bdst1 = (uint32_t)(OFF_B + s * BPITCH + half * 16);
        bsz1 = valid ? 16u : 0u;
    }

    float acc[2][8][4];
    #pragma unroll
    for (int mt = 0; mt < 2; ++mt)
        #pragma unroll
        for (int nf = 0; nf < 8; ++nf)
            #pragma unroll
            for (int r = 0; r < 4; ++r) acc[mt][nf][r] = 0.f;

    auto issue = [&](int c) {
        const uint32_t bb = smb + (c % 3) * BUFSZ;
        const unsigned char* as = asrc0 + c * 16384;
        cpasync16z(bb + adst0,                 as,         16);
        cpasync16z(bb + adst0 + 32 * APITCH,   as + 4096,  16);
        cpasync16z(bb + adst0 + 64 * APITCH,   as + 8192,  16);
        cpasync16z(bb + adst0 + 96 * APITCH,   as + 12288, 16);
        cpasync16z(bb + bdst0, bsrc0 + c * 32, bsz0);
        if (t < 96) cpasync16z(bb + bdst1, bsrc1 + c * 32, bsz1);
        asm volatile("cp.async.commit_group;" ::: "memory");
    };

    auto compute = [&](int c) {
        const uint32_t bb = smb + (c % 3) * BUFSZ;
        #pragma unroll
        for (int tap = 0; tap < 4; ++tap) {
            const uint32_t koff = tap * 32;
            const int dlt = (tap >> 1) * 40 + (tap & 1);
            uint32_t Ah[2][4], Bh[8][2];
            ldmx4(Ah[0], bb + aoff + koff);
            ldmx4(Ah[1], bb + aoff + 16 * APITCH + koff);
            #pragma unroll
            for (int g = 0; g < 4; ++g) {
                uint32_t r[4];
                ldmx4(r, bb + OFF_B + boff + (dlt + g * 16) * BPITCH);
                Bh[2*g][0] = r[0]; Bh[2*g][1] = r[1];
                Bh[2*g+1][0] = r[2]; Bh[2*g+1][1] = r[3];
            }
            #pragma unroll
            for (int mt = 0; mt < 2; ++mt)
                #pragma unroll
                for (int nf = 0; nf < 8; ++nf)
                    mma16816(acc[mt][nf], Ah[mt], Bh[nf]);
        }
    };

    issue(0);
    issue(1);
    for (int c = 0; c < 16; ++c) {
        if (c == 15) {
            asm volatile("cp.async.wait_group 0;" ::: "memory");
        } else {
            asm volatile("cp.async.wait_group 1;" ::: "memory");
        }
        __syncthreads();
        if (c < 14) issue(c + 2);
        compute(c);
    }
    __syncthreads();

    __half* sT = (__half*)sm;
    float bia[2][2];
    #pragma unroll
    for (int mt = 0; mt < 2; ++mt) {
        int mb = wm * 32 + mt * 16 + (l >> 2);
        bia[mt][0] = __ldg(bias + mb);
        bia[mt][1] = __ldg(bias + mb + 8);
    }
    #pragma unroll
    for (int mt = 0; mt < 2; ++mt)
        #pragma unroll
        for (int nf = 0; nf < 8; ++nf)
            #pragma unroll
            for (int r = 0; r < 4; ++r) {
                int m = wm * 32 + mt * 16 + (l >> 2) + ((r >> 1) ? 8 : 0);
                int n = wn * 64 + nf * 8 + 2 * (l & 3) + (r & 1);
                float v = acc[mt][nf][r] + bia[mt][r >> 1];
                v = v > 0.f ? v : 0.f;
                sT[n * TPITCH + m] = __float2half(v);
            }
    __syncthreads();
    {
        const int row = t >> 1, hf = t & 1;
        const uint4* src = (const uint4*)(sT + row * TPITCH + hf * 64);
        uint4* dst = (uint4*)(g_xh + ((size_t)b * ROWS40 + nbase + row) * OC1 + hf * 64);
        #pragma unroll
        for (int seg = 0; seg < 8; ++seg) dst[seg] = src[seg];
    }
}

// ---------------------------------------------------------------------------
// K2: smem-staged approx diff-conv; top-2 positions per 8-image-row tile.
// (frozen — measured 70us)
// ---------------------------------------------------------------------------
#define K2_SMEM (360 * 256)

__global__ __launch_bounds__(256) void cls_topk_kernel(
    const float* __restrict__ Wc, const float* __restrict__ bc)
{
    extern __shared__ __align__(16) unsigned char smx[];
    __shared__ __align__(16) __half2 swd[16 * 64];
    __shared__ float rv1[256], rv2[256];
    __shared__ int   rp1[256], rp2[256];
    const int tb = blockIdx.x, b = blockIdx.y, t = threadIdx.x;
    const int y0 = tb * 8;
    const int nrows = (38 - y0 < 8) ? 38 - y0 : 8;
    const int npos = nrows * 38;
    const int base40 = y0 * 40;
    const uint32_t smbx = smem_u32(smx);

    #pragma unroll
    for (int i = 0; i < 4; ++i) {
        int e = t + i * 256;
        int combo = e >> 6, ocp = e & 63;
        int tap = combo >> 2, ch = combo & 3;
        int oc0 = ocp * 2;
        float d0 = Wc[(ch + 4) * 512 + oc0 * 4 + tap] - Wc[ch * 512 + oc0 * 4 + tap];
        float d1 = Wc[(ch + 4) * 512 + (oc0 + 1) * 4 + tap]
                 - Wc[ch * 512 + (oc0 + 1) * 4 + tap];
        swd[combo * 64 + ocp] = __floats2half2_rn(d0, d1);
    }

    #pragma unroll
    for (int i = 0; i < 23; ++i) {
        int e = t + i * 256;
        if (e < 5760) {
            int r = e >> 4, q = e & 15;
            cpasync16z(smbx + r * 256 + ((q ^ (r & 15)) << 4),
                       g_xh + ((size_t)b * ROWS40 + base40 + r) * OC1 + q * 8, 16);
        }
    }
    asm volatile("cp.async.commit_group;" ::: "memory");
    asm volatile("cp.async.wait_group 0;" ::: "memory");
    __syncthreads();

    float bd[4];
    #pragma unroll
    for (int a = 0; a < 4; ++a) bd[a] = bc[a + 4] - bc[a];

    float v1 = -1e30f, v2 = -1e30f;
    int p1 = 0x7fffffff, p2 = 0x7fffffff;
    #pragma unroll
    for (int it = 0; it < 2; ++it) {
        int pl = t + it * 256;
        if (pl < npos) {
            int iy = pl / 38, ix = pl - iy * 38;
            int r0 = iy * 40 + ix;
            int rb[4] = {r0, r0 + 1, r0 + 40, r0 + 41};
            float facc[4] = {0.f, 0.f, 0.f, 0.f};
            #pragma unroll
            for (int qb = 0; qb < 4; ++qb) {
                __half2 hacc[4];
                #pragma unroll
                for (int ch = 0; ch < 4; ++ch) hacc[ch] = __float2half2_rn(0.f);
                #pragma unroll
                for (int u = 0; u < 4; ++u) {
                    int q = qb * 4 + u;
                    __half2 xr[4][4];
                    #pragma unroll
                    for (int tap = 0; tap < 4; ++tap)
                        *(uint4*)xr[tap] = *(const uint4*)(smx + rb[tap] * 256
                                            + ((q ^ (rb[tap] & 15)) << 4));
                    #pragma unroll
                    for (int ch = 0; ch < 4; ++ch) {
                        #pragma unroll
                        for (int tap = 0; tap < 4; ++tap) {
                            uint4 wv = *(const uint4*)&swd[(tap * 4 + ch) * 64 + q * 4];
                            __half2* wh = (__half2*)&wv;
                            #pragma unroll
                            for (int k = 0; k < 4; ++k)
                                hacc[ch] = __hfma2(xr[tap][k], wh[k], hacc[ch]);
                        }
                    }
                }
                #pragma unroll
                for (int ch = 0; ch < 4; ++ch) {
                    float2 f = __half22float2(hacc[ch]);
                    facc[ch] += f.x + f.y;
                }
            }
            float pv = facc[0] + bd[0];
            #pragma unroll
            for (int ch = 1; ch < 4; ++ch) {
                float v = facc[ch] + bd[ch];
                if (v > pv) pv = v;
            }
            int p = (y0 + iy) * 38 + ix;
            if (better(pv, p, v1, p1)) { v2 = v1; p2 = p1; v1 = pv; p1 = p; }
            else if (better(pv, p, v2, p2)) { v2 = pv; p2 = p; }
        }
    }
    rv1[t] = v1; rp1[t] = p1; rv2[t] = v2; rp2[t] = p2;
    __syncthreads();
    for (int s = 128; s > 0; s >>= 1) {
        if (t < s) {
            float a1 = rv1[t], a2 = rv2[t];
            int   e1 = rp1[t], e2 = rp2[t];
            float w1 = rv1[t + s], w2 = rv2[t + s];
            int   q1 = rp1[t + s], q2 = rp2[t + s];
            float n1, n2; int m1, m2;
            if (better(a1, e1, w1, q1)) {
                n1 = a1; m1 = e1;
                if (better(w1, q1, a2, e2)) { n2 = w1; m2 = q1; }
                else                        { n2 = a2; m2 = e2; }
            } else {
                n1 = w1; m1 = q1;
                if (better(a1, e1, w2, q2)) { n2 = a1; m2 = e1; }
                else                        { n2 = w2; m2 = q2; }
            }
            rv1[t] = n1; rp1[t] = m1; rv2[t] = n2; rp2[t] = m2;
        }
        __syncthreads();
    }
    if (t == 0) {
        g_cp[b * NCAND + tb * 2]     = rp1[0];
        g_cp[b * NCAND + tb * 2 + 1] = rp2[0];
    }
}

// ---------------------------------------------------------------------------
// K3: fused exact re-score of ALL 10 candidates (one block/batch, W1 read
// once per thread, patches staged in dyn smem) + exact winner box.
// ---------------------------------------------------------------------------
#define K3_SMEM (NCAND * 2304 * 4)   /* 92160 B */

__global__ __launch_bounds__(256) void box_kernel(
    const float* __restrict__ in, const float* __restrict__ W1,
    const float* __restrict__ b1,
    const float* __restrict__ Wc, const float* __restrict__ bc,
    const float* __restrict__ Wb, const float* __restrict__ bb,
    const float* __restrict__ anchors, const float* __restrict__ im_info,
    float* __restrict__ out)
{
    extern __shared__ float dsm[];               // sfeat[10][2304] / reuse
    __shared__ int   spos[NCAND];
    __shared__ float ssc[NCAND * 4];
    __shared__ float sxa[512];
    __shared__ float sred[4][128];
    __shared__ float sBestV;
    __shared__ int   sBestF;

    const int b = blockIdx.x, t = threadIdx.x;
    const int half = t >> 7, oc = t & 127;

    if (t < NCAND) spos[t] = g_cp[b * NCAND + t];
    __syncthreads();

    // ---- stage all 10 patches ----
    #pragma unroll
    for (int i = 0; i < 90; ++i) {
        int e = t + i * 256;
        int cand = e / 2304, r = e - cand * 2304;
        int ic = r / 9, p = r - ic * 9;
        int pos = spos[cand];
        int rr = pos / 38 - 1 + p / 3, cc = pos % 38 - 1 + p % 3;
        dsm[e] = (rr >= 0 && rr < 38 && cc >= 0 && cc < 38)
               ? in[((size_t)(b * ICH + ic) * 38 + rr) * 38 + cc] : 0.f;
    }
    __syncthreads();

    // ---- exact conv1 partials at 4 tap positions, all candidates ----
    float xa[NCAND][4];
    #pragma unroll
    for (int c = 0; c < NCAND; ++c)
        #pragma unroll
        for (int j = 0; j < 4; ++j) xa[c][j] = 0.f;
    const float4* wr = (const float4*)(W1 + oc * 1024) + half * 128;
    for (int icl = 0; icl < 128; ++icl) {
        float4 w = wr[icl];
        int ic = half * 128 + icl;
        #pragma unroll
        for (int c = 0; c < NCAND; ++c) {
            const float* sf = &dsm[c * 2304 + ic * 9];
            float s0 = sf[0], s1 = sf[1], s2 = sf[2];
            float s3 = sf[3], s4 = sf[4], s5 = sf[5];
            float s6 = sf[6], s7 = sf[7], s8 = sf[8];
            xa[c][0] += w.x * s0 + w.y * s1 + w.z * s3 + w.w * s4;
            xa[c][1] += w.x * s1 + w.y * s2 + w.z * s4 + w.w * s5;
            xa[c][2] += w.x * s3 + w.y * s4 + w.z * s6 + w.w * s7;
            xa[c][3] += w.x * s4 + w.y * s5 + w.z * s7 + w.w * s8;
        }
    }
    __syncthreads();   // done reading sfeat; reuse dsm

    float* sxa10 = dsm;                 // [10][128][4]
    float* red10 = dsm + NCAND * 512;   // [10][4][128]
    if (half == 0)
        #pragma unroll
        for (int c = 0; c < NCAND; ++c)
            #pragma unroll
            for (int j = 0; j < 4; ++j) sxa10[c * 512 + oc * 4 + j] = xa[c][j];
    __syncthreads();
    if (half == 1)
        #pragma unroll
        for (int c = 0; c < NCAND; ++c)
            #pragma unroll
            for (int j = 0; j < 4; ++j) sxa10[c * 512 + oc * 4 + j] += xa[c][j];
    __syncthreads();

    if (half == 0) {
        float wd[4][4];
        #pragma unroll
        for (int ch = 0; ch < 4; ++ch)
            #pragma unroll
            for (int tp = 0; tp < 4; ++tp)
                wd[ch][tp] = Wc[(ch + 4) * 512 + oc * 4 + tp]
                           - Wc[ch * 512 + oc * 4 + tp];
        float bv1 = b1[oc];
        #pragma unroll
        for (int c = 0; c < NCAND; ++c) {
            float x0 = fmaxf(sxa10[c * 512 + oc * 4 + 0] + bv1, 0.f);
            float x1 = fmaxf(sxa10[c * 512 + oc * 4 + 1] + bv1, 0.f);
            float x2 = fmaxf(sxa10[c * 512 + oc * 4 + 2] + bv1, 0.f);
            float x3 = fmaxf(sxa10[c * 512 + oc * 4 + 3] + bv1, 0.f);
            #pragma unroll
            for (int ch = 0; ch < 4; ++ch)
                red10[c * 512 + ch * 128 + oc] =
                    wd[ch][0] * x0 + wd[ch][1] * x1 + wd[ch][2] * x2 + wd[ch][3] * x3;
        }
    }
    __syncthreads();
    if (t < NCAND * 4) {
        int c = t >> 2, ch = t & 3;
        float s = 0.f;
        #pragma unroll 8
        for (int k = 0; k < 128; ++k) s += red10[c * 512 + ch * 128 + k];
        ssc[t] = s + bc[ch + 4] - bc[ch];
    }
    __syncthreads();
    if (t == 0) {
        float bv = -1e30f; int bf = 0x7fffffff;
        for (int c = 0; c < NCAND; ++c) {
            int pos = spos[c];
            #pragma unroll
            for (int ch = 0; ch < 4; ++ch) {
                float v = ssc[c * 4 + ch];
                int f = ch * KPOS + pos;
                if (v > bv || (v == bv && f < bf)) { bv = v; bf = f; }
            }
        }
        sBestV = bv; sBestF = bf;
    }
    __syncthreads();

    // ---- exact x at decoded proposal position kp = f>>2, then box ----
    const int f = sBestF;
    const int kp = f >> 2, ap = f & 3;
    const int hp = kp / 38, wp = kp % 38;
    #pragma unroll
    for (int i = 0; i < 9; ++i) {
        int e = t + i * 256;
        if (e < 2304) {
            int ic = e / 9, p = e - ic * 9;
            int rr = hp - 1 + p / 3, cc = wp - 1 + p % 3;
            dsm[e] = (rr >= 0 && rr < 38 && cc >= 0 && cc < 38)
                   ? in[((size_t)(b * ICH + ic) * 38 + rr) * 38 + cc] : 0.f;
        }
    }
    __syncthreads();
    float xw[4] = {0.f, 0.f, 0.f, 0.f};
    for (int icl = 0; icl < 128; ++icl) {
        float4 w = wr[icl];
        int ic = half * 128 + icl;
        const float* sf = &dsm[ic * 9];
        float s0 = sf[0], s1 = sf[1], s2 = sf[2];
        float s3 = sf[3], s4 = sf[4], s5 = sf[5];
        float s6 = sf[6], s7 = sf[7], s8 = sf[8];
        xw[0] += w.x * s0 + w.y * s1 + w.z * s3 + w.w * s4;
        xw[1] += w.x * s1 + w.y * s2 + w.z * s4 + w.w * s5;
        xw[2] += w.x * s3 + w.y * s4 + w.z * s6 + w.w * s7;
        xw[3] += w.x * s4 + w.y * s5 + w.z * s7 + w.w * s8;
    }
    if (half == 0)
        #pragma unroll
        for (int j = 0; j < 4; ++j) sxa[oc * 4 + j] = xw[j];
    __syncthreads();
    if (half == 1)
        #pragma unroll
        for (int j = 0; j < 4; ++j) sxa[oc * 4 + j] += xw[j];
    __syncthreads();

    if (half == 0) {
        float bv1 = b1[oc];
        float x0 = fmaxf(sxa[oc * 4 + 0] + bv1, 0.f);
        float x1 = fmaxf(sxa[oc * 4 + 1] + bv1, 0.f);
        float x2 = fmaxf(sxa[oc * 4 + 2] + bv1, 0.f);
        float x3 = fmaxf(sxa[oc * 4 + 3] + bv1, 0.f);
        #pragma unroll
        for (int j = 0; j < 4; ++j) {
            const float* wq = Wb + (ap * 4 + j) * 512 + oc * 4;
            sred[j][oc] = x0 * wq[0] + x1 * wq[1] + x2 * wq[2] + x3 * wq[3];
        }
    }
    __syncthreads();
    if (t < 4) {
        float s = 0.f;
        #pragma unroll 8
        for (int k = 0; k < 128; ++k) s += sred[t][k];
        s += bb[ap * 4 + t];
        float shift = (t & 1) ? hp * 16.f : wp * 16.f;
        float scv = im_info[0];
        float box = (anchors[ap * 4 + t] + shift + s) * scv;
        out[b * 9 + t]     = truncf(box / scv);
        out[b * 9 + 4 + t] = box;
    }
    if (t == 4) out[b * 9 + 8] = 1.f / (1.f + expf(-sBestV));
}

// ---------------------------------------------------------------------------
// K4: proposal loss.
// ---------------------------------------------------------------------------
__global__ void loss_kernel(const float* __restrict__ gt,
                            const int* __restrict__ central,
                            float* __restrict__ out, int out_size)
{
    int idx = central[0];
    bool valid = idx < BATCH;
    int ix = idx < 0 ? 0 : (idx > BATCH - 1 ? BATCH - 1 : idx);
    float vb0 = out[ix * 9 + 4], vb1 = out[ix * 9 + 5];
    float vb2 = out[ix * 9 + 6], vb3 = out[ix * 9 + 7];
    float vs  = out[ix * 9 + 8];
    float xi1 = fmaxf(gt[0], vb0);
    float yi1 = fmaxf(gt[1], vb1);
    float xi2 = fmaxf(gt[2], vb2);
    float yi2 = fmaxf(gt[3], vb3);
    float inter = (xi2 - xi1) * (yi2 - yi1);
    float a1 = (gt[2] - gt[0]) * (gt[3] - gt[1]);
    float a2 = (vb2 - vb0) * (vb3 - vb1);
    float iou = inter / (a1 + a2 - inter);
    float lv = (iou > 0.7f) ? -logf(vs + 1e-5f) : -logf(1.f - vs + 1e-5f);
    out[out_size - 1] = valid ? lv : 0.f;
}

// ---------------------------------------------------------------------------
extern "C" void kernel_launch(void* const* d_in, const int* in_sizes, int n_in,
                              void* d_out, int out_size)
{
    const float* base_feat = (const float*)d_in[0];
    const int*   central   = (const int*)  d_in[1];
    const float* im_info   = (const float*)d_in[2];
    const float* gt_boxes  = (const float*)d_in[3];
    const float* W1        = (const float*)d_in[4];
    const float* b1        = (const float*)d_in[5];
    const float* Wc        = (const float*)d_in[6];
    const float* bc        = (const float*)d_in[7];
    const float* Wb        = (const float*)d_in[8];
    const float* bb        = (const float*)d_in[9];
    const float* anchors   = (const float*)d_in[10];
    float* out = (float*)d_out;

    cudaFuncSetAttribute(conv1_tc_kernel,
                         cudaFuncAttributeMaxDynamicSharedMemorySize, SMEM_TC);
    cudaFuncSetAttribute(cls_topk_kernel,
                         cudaFuncAttributeMaxDynamicSharedMemorySize, K2_SMEM);
    cudaFuncSetAttribute(box_kernel,
                         cudaFuncAttributeMaxDynamicSharedMemorySize, K3_SMEM);

    prep_w_kernel<<<256, 256>>>(W1);
    prep_in_kernel<<<dim3(19, 8, BATCH), 256>>>(base_feat);
    conv1_tc_kernel<<<BATCH * 13, 256, SMEM_TC>>>(b1);
    cls_topk_kernel<<<dim3(5, BATCH), 256, K2_SMEM>>>(Wc, bc);
    box_kernel<<<BATCH, 256, K3_SMEM>>>(base_feat, W1, b1, Wc, bc,
                                        Wb, bb, anchors, im_info, out);
    loss_kernel<<<1, 1>>>(gt_boxes, central, out, out_size);
}

// round 16
// speedup vs baseline: 1.3934x; 1.0302x over previous
#include <cuda_runtime.h>
#include <cuda_fp16.h>
#include <math.h>
#include <cstdint>

#define BATCH 300
#define ICH   256
#define OC1   128
#define KPOS  1444
#define ROWS40 1664
#define NCAND 10

typedef unsigned long long ull;

// ------------------- device scratch -------------------
__device__ __align__(16) __half g_xh[(size_t)BATCH * ROWS40 * OC1];
__device__ int g_cp[BATCH * NCAND];            // candidate positions (top-2 x 5 tiles)
__device__ __align__(16) unsigned char g_Ah[16 * 16384];
__device__ __half g_pH[(size_t)BATCH * KPOS * ICH];

__device__ __forceinline__ uint32_t smem_u32(const void* p) {
    return (uint32_t)__cvta_generic_to_shared(p);
}
__device__ __forceinline__ void ldmx4(uint32_t* r, uint32_t addr) {
    asm volatile("ldmatrix.sync.aligned.m8n8.x4.shared.b16 {%0,%1,%2,%3}, [%4];"
        : "=r"(r[0]), "=r"(r[1]), "=r"(r[2]), "=r"(r[3]) : "r"(addr));
}
__device__ __forceinline__ void mma16816(float* d, const uint32_t* a, const uint32_t* b) {
    asm volatile("mma.sync.aligned.m16n8k16.row.col.f32.f16.f16.f32 "
        "{%0,%1,%2,%3},{%4,%5,%6,%7},{%8,%9},{%0,%1,%2,%3};"
        : "+f"(d[0]), "+f"(d[1]), "+f"(d[2]), "+f"(d[3])
        : "r"(a[0]), "r"(a[1]), "r"(a[2]), "r"(a[3]), "r"(b[0]), "r"(b[1]));
}
__device__ __forceinline__ void cpasync16z(uint32_t dst, const void* src, uint32_t sz) {
    asm volatile("cp.async.cg.shared.global [%0], [%1], 16, %2;"
        :: "r"(dst), "l"(src), "r"(sz));
}
__device__ __forceinline__ bool better(float v, int p, float w, int q) {
    return v > w || (v == w && p < q);
}

#define FMA2(acc, a, s) \
    asm("fma.rn.f32x2 %0, %1, %2, %0;" : "+l"(acc) : "l"(a), "l"(s))
#define PACK2(d, f) \
    asm("mov.b64 %0, {%1, %1};" : "=l"(d) : "f"(f))
#define UNPACK2(lo, hi, v) \
    asm("mov.b64 {%0, %1}, %2;" : "=f"(lo), "=f"(hi) : "l"(v))

// ---------------------------------------------------------------------------
// K0a: W1 -> fp16 hi image [c][oc][64k], k = tap*16 + icL.
// ---------------------------------------------------------------------------
__global__ __launch_bounds__(256) void prep_w_kernel(const float* __restrict__ W1) {
    int p = blockIdx.x * 256 + threadIdx.x;
    int oc = p >> 9;
    int kk = (p & 511) << 1;
    int c = kk >> 6, k2 = kk & 63;
    int tap = k2 >> 4, icL = k2 & 15;
    __half h0 = __float2half(W1[oc * 1024 + (c * 16 + icL) * 4 + tap]);
    __half h1 = __float2half(W1[oc * 1024 + (c * 16 + icL + 1) * 4 + tap]);
    uint32_t uh = ((uint32_t)__half_as_ushort(h1) << 16) | __half_as_ushort(h0);
    *(uint32_t*)(g_Ah + (uint32_t)(c * 16384 + oc * 128 + k2 * 2)) = uh;
}

// ---------------------------------------------------------------------------
// K0b: transpose input: [b][ic][1444] fp32 -> [b][pos][ic] fp16.
// ---------------------------------------------------------------------------
__global__ __launch_bounds__(256) void prep_in_kernel(const float* __restrict__ in) {
    __shared__ float st[32][77];
    const int pt = blockIdx.x, icb = blockIdx.y, b = blockIdx.z;
    const int t = threadIdx.x;
    const float* src = in + ((size_t)(b * ICH + icb * 32) * KPOS) + pt * 76;
    #pragma unroll
    for (int i = 0; i < 10; ++i) {
        int e = t + i * 256;
        if (e < 2432) {
            int icL = e / 76, s = e - icL * 76;
            st[icL][s] = src[(size_t)icL * KPOS + s];
        }
    }
    __syncthreads();
    #pragma unroll
    for (int i = 0; i < 10; ++i) {
        int e = t + i * 256;
        if (e < 2432) {
            int posL = e >> 5, icL = e & 31;
            size_t d = (size_t)(b * KPOS + pt * 76 + posL) * ICH + icb * 32 + icL;
            g_pH[d] = __float2half(st[icL][posL]);
        }
    }
}

// ---------------------------------------------------------------------------
// K1: conv1, tap-decomposed 1-pass fp16, hoisted copy descriptors. (frozen)
// ---------------------------------------------------------------------------
#define APITCH 144
#define BPITCH 48
#define OFF_B  18432
#define BUFSZ  35328
#define SMEM_TC (3 * BUFSZ)
#define TPITCH 136

__global__ __launch_bounds__(256, 2) void conv1_tc_kernel(
    const float* __restrict__ bias)
{
    extern __shared__ __align__(16) unsigned char sm[];
    const uint32_t smb = smem_u32(sm);
    const int t = threadIdx.x;
    const int b = blockIdx.x / 13;
    const int tile = blockIdx.x - b * 13;
    const int nbase = tile * 128;

    const int wid = t >> 5, l = t & 31;
    const int wm = wid & 3, wn = wid >> 2;
    const uint32_t aoff = (uint32_t)((wm * 32 + (l & 15)) * APITCH + ((l >> 4) & 1) * 16);
    const uint32_t boff = (uint32_t)((wn * 64 + (l & 7) + ((l >> 4) & 1) * 8) * BPITCH
                                     + ((l >> 3) & 1) * 16);

    const uint32_t adst0 = (uint32_t)((t >> 3) * APITCH + (t & 7) * 16);
    const unsigned char* asrc0 = g_Ah + t * 16;
    const unsigned char* bsrc0;
    const unsigned char* bsrc1 = nullptr;
    uint32_t bdst0, bdst1 = 0, bsz0, bsz1 = 0;
    {
        int e = t;
        int s = e >> 1, half = e & 1;
        int m = nbase - 40 + s;
        int iy = m / 40, px = m - iy * 40;
        bool valid = (m >= 0) && (iy < 38) && (px >= 1) && (px <= 38);
        size_t si = valid ? ((size_t)(b * KPOS + iy * 38 + px - 1) * ICH + half * 8) : 0;
        bsrc0 = (const unsigned char*)(g_pH + si);
        bdst0 = (uint32_t)(OFF_B + s * BPITCH + half * 16);
        bsz0 = valid ? 16u : 0u;
    }
    if (t < 96) {
        int e = t + 256;
        int s = e >> 1, half = e & 1;
        int m = nbase - 40 + s;
        int iy = m / 40, px = m - iy * 40;
        bool valid = (m >= 0) && (iy < 38) && (px >= 1) && (px <= 38);
        size_t si = valid ? ((size_t)(b * KPOS + iy * 38 + px - 1) * ICH + half * 8) : 0;
        bsrc1 = (const unsigned char*)(g_pH + si);
        bdst1 = (uint32_t)(OFF_B + s * BPITCH + half * 16);
        bsz1 = valid ? 16u : 0u;
    }

    float acc[2][8][4];
    #pragma unroll
    for (int mt = 0; mt < 2; ++mt)
        #pragma unroll
        for (int nf = 0; nf < 8; ++nf)
            #pragma unroll
            for (int r = 0; r < 4; ++r) acc[mt][nf][r] = 0.f;

    auto issue = [&](int c) {
        const uint32_t bb = smb + (c % 3) * BUFSZ;
        const unsigned char* as = asrc0 + c * 16384;
        cpasync16z(bb + adst0,                 as,         16);
        cpasync16z(bb + adst0 + 32 * APITCH,   as + 4096,  16);
        cpasync16z(bb + adst0 + 64 * APITCH,   as + 8192,  16);
        cpasync16z(bb + adst0 + 96 * APITCH,   as + 12288, 16);
        cpasync16z(bb + bdst0, bsrc0 + c * 32, bsz0);
        if (t < 96) cpasync16z(bb + bdst1, bsrc1 + c * 32, bsz1);
        asm volatile("cp.async.commit_group;" ::: "memory");
    };

    auto compute = [&](int c) {
        const uint32_t bb = smb + (c % 3) * BUFSZ;
        #pragma unroll
        for (int tap = 0; tap < 4; ++tap) {
            const uint32_t koff = tap * 32;
            const int dlt = (tap >> 1) * 40 + (tap & 1);
            uint32_t Ah[2][4], Bh[8][2];
            ldmx4(Ah[0], bb + aoff + koff);
            ldmx4(Ah[1], bb + aoff + 16 * APITCH + koff);
            #pragma unroll
            for (int g = 0; g < 4; ++g) {
                uint32_t r[4];
                ldmx4(r, bb + OFF_B + boff + (dlt + g * 16) * BPITCH);
                Bh[2*g][0] = r[0]; Bh[2*g][1] = r[1];
                Bh[2*g+1][0] = r[2]; Bh[2*g+1][1] = r[3];
            }
            #pragma unroll
            for (int mt = 0; mt < 2; ++mt)
                #pragma unroll
                for (int nf = 0; nf < 8; ++nf)
                    mma16816(acc[mt][nf], Ah[mt], Bh[nf]);
        }
    };

    issue(0);
    issue(1);
    for (int c = 0; c < 16; ++c) {
        if (c == 15) {
            asm volatile("cp.async.wait_group 0;" ::: "memory");
        } else {
            asm volatile("cp.async.wait_group 1;" ::: "memory");
        }
        __syncthreads();
        if (c < 14) issue(c + 2);
        compute(c);
    }
    __syncthreads();

    __half* sT = (__half*)sm;
    float bia[2][2];
    #pragma unroll
    for (int mt = 0; mt < 2; ++mt) {
        int mb = wm * 32 + mt * 16 + (l >> 2);
        bia[mt][0] = __ldg(bias + mb);
        bia[mt][1] = __ldg(bias + mb + 8);
    }
    #pragma unroll
    for (int mt = 0; mt < 2; ++mt)
        #pragma unroll
        for (int nf = 0; nf < 8; ++nf)
            #pragma unroll
            for (int r = 0; r < 4; ++r) {
                int m = wm * 32 + mt * 16 + (l >> 2) + ((r >> 1) ? 8 : 0);
                int n = wn * 64 + nf * 8 + 2 * (l & 3) + (r & 1);
                float v = acc[mt][nf][r] + bia[mt][r >> 1];
                v = v > 0.f ? v : 0.f;
                sT[n * TPITCH + m] = __float2half(v);
            }
    __syncthreads();
    {
        const int row = t >> 1, hf = t & 1;
        const uint4* src = (const uint4*)(sT + row * TPITCH + hf * 64);
        uint4* dst = (uint4*)(g_xh + ((size_t)b * ROWS40 + nbase + row) * OC1 + hf * 64);
        #pragma unroll
        for (int seg = 0; seg < 8; ++seg) dst[seg] = src[seg];
    }
}

// ---------------------------------------------------------------------------
// K2: smem-staged approx diff-conv; top-2 positions per 8-image-row tile.
// (frozen — measured 70us)
// ---------------------------------------------------------------------------
#define K2_SMEM (360 * 256)

__global__ __launch_bounds__(256) void cls_topk_kernel(
    const float* __restrict__ Wc, const float* __restrict__ bc)
{
    extern __shared__ __align__(16) unsigned char smx[];
    __shared__ __align__(16) __half2 swd[16 * 64];
    __shared__ float rv1[256], rv2[256];
    __shared__ int   rp1[256], rp2[256];
    const int tb = blockIdx.x, b = blockIdx.y, t = threadIdx.x;
    const int y0 = tb * 8;
    const int nrows = (38 - y0 < 8) ? 38 - y0 : 8;
    const int npos = nrows * 38;
    const int base40 = y0 * 40;
    const uint32_t smbx = smem_u32(smx);

    #pragma unroll
    for (int i = 0; i < 4; ++i) {
        int e = t + i * 256;
        int combo = e >> 6, ocp = e & 63;
        int tap = combo >> 2, ch = combo & 3;
        int oc0 = ocp * 2;
        float d0 = Wc[(ch + 4) * 512 + oc0 * 4 + tap] - Wc[ch * 512 + oc0 * 4 + tap];
        float d1 = Wc[(ch + 4) * 512 + (oc0 + 1) * 4 + tap]
                 - Wc[ch * 512 + (oc0 + 1) * 4 + tap];
        swd[combo * 64 + ocp] = __floats2half2_rn(d0, d1);
    }

    #pragma unroll
    for (int i = 0; i < 23; ++i) {
        int e = t + i * 256;
        if (e < 5760) {
            int r = e >> 4, q = e & 15;
            cpasync16z(smbx + r * 256 + ((q ^ (r & 15)) << 4),
                       g_xh + ((size_t)b * ROWS40 + base40 + r) * OC1 + q * 8, 16);
        }
    }
    asm volatile("cp.async.commit_group;" ::: "memory");
    asm volatile("cp.async.wait_group 0;" ::: "memory");
    __syncthreads();

    float bd[4];
    #pragma unroll
    for (int a = 0; a < 4; ++a) bd[a] = bc[a + 4] - bc[a];

    float v1 = -1e30f, v2 = -1e30f;
    int p1 = 0x7fffffff, p2 = 0x7fffffff;
    #pragma unroll
    for (int it = 0; it < 2; ++it) {
        int pl = t + it * 256;
        if (pl < npos) {
            int iy = pl / 38, ix = pl - iy * 38;
            int r0 = iy * 40 + ix;
            int rb[4] = {r0, r0 + 1, r0 + 40, r0 + 41};
            float facc[4] = {0.f, 0.f, 0.f, 0.f};
            #pragma unroll
            for (int qb = 0; qb < 4; ++qb) {
                __half2 hacc[4];
                #pragma unroll
                for (int ch = 0; ch < 4; ++ch) hacc[ch] = __float2half2_rn(0.f);
                #pragma unroll
                for (int u = 0; u < 4; ++u) {
                    int q = qb * 4 + u;
                    __half2 xr[4][4];
                    #pragma unroll
                    for (int tap = 0; tap < 4; ++tap)
                        *(uint4*)xr[tap] = *(const uint4*)(smx + rb[tap] * 256
                                            + ((q ^ (rb[tap] & 15)) << 4));
                    #pragma unroll
                    for (int ch = 0; ch < 4; ++ch) {
                        #pragma unroll
                        for (int tap = 0; tap < 4; ++tap) {
                            uint4 wv = *(const uint4*)&swd[(tap * 4 + ch) * 64 + q * 4];
                            __half2* wh = (__half2*)&wv;
                            #pragma unroll
                            for (int k = 0; k < 4; ++k)
                                hacc[ch] = __hfma2(xr[tap][k], wh[k], hacc[ch]);
                        }
                    }
                }
                #pragma unroll
                for (int ch = 0; ch < 4; ++ch) {
                    float2 f = __half22float2(hacc[ch]);
                    facc[ch] += f.x + f.y;
                }
            }
            float pv = facc[0] + bd[0];
            #pragma unroll
            for (int ch = 1; ch < 4; ++ch) {
                float v = facc[ch] + bd[ch];
                if (v > pv) pv = v;
            }
            int p = (y0 + iy) * 38 + ix;
            if (better(pv, p, v1, p1)) { v2 = v1; p2 = p1; v1 = pv; p1 = p; }
            else if (better(pv, p, v2, p2)) { v2 = pv; p2 = p; }
        }
    }
    rv1[t] = v1; rp1[t] = p1; rv2[t] = v2; rp2[t] = p2;
    __syncthreads();
    for (int s = 128; s > 0; s >>= 1) {
        if (t < s) {
            float a1 = rv1[t], a2 = rv2[t];
            int   e1 = rp1[t], e2 = rp2[t];
            float w1 = rv1[t + s], w2 = rv2[t + s];
            int   q1 = rp1[t + s], q2 = rp2[t + s];
            float n1, n2; int m1, m2;
            if (better(a1, e1, w1, q1)) {
                n1 = a1; m1 = e1;
                if (better(w1, q1, a2, e2)) { n2 = w1; m2 = q1; }
                else                        { n2 = a2; m2 = e2; }
            } else {
                n1 = w1; m1 = q1;
                if (better(a1, e1, w2, q2)) { n2 = a1; m2 = e1; }
                else                        { n2 = w2; m2 = q2; }
            }
            rv1[t] = n1; rp1[t] = m1; rv2[t] = n2; rp2[t] = m2;
        }
        __syncthreads();
    }
    if (t == 0) {
        g_cp[b * NCAND + tb * 2]     = rp1[0];
        g_cp[b * NCAND + tb * 2 + 1] = rp2[0];
    }
}

// ---------------------------------------------------------------------------
// K3: fused exact re-score of ALL 10 candidates with packed f32x2 FMA
// (candidate-pair interleaved patches -> LDS.64 + fma.rn.f32x2),
// then exact winner box. One block/batch.
// ---------------------------------------------------------------------------
#define K3_SMEM (NCAND * 2304 * 4)   /* 92160 B: spatch [256 ic][9 p][10 cand] */

__global__ __launch_bounds__(256) void box_kernel(
    const float* __restrict__ in, const float* __restrict__ W1,
    const float* __restrict__ b1,
    const float* __restrict__ Wc, const float* __restrict__ bc,
    const float* __restrict__ Wb, const float* __restrict__ bb,
    const float* __restrict__ anchors, const float* __restrict__ im_info,
    float* __restrict__ out)
{
    extern __shared__ float dsm[];
    __shared__ int   spos[NCAND];
    __shared__ float ssc[NCAND * 4];
    __shared__ float sxa[512];
    __shared__ float sred[4][128];
    __shared__ float sBestV;
    __shared__ int   sBestF;

    const int b = blockIdx.x, t = threadIdx.x;
    const int half = t >> 7, oc = t & 127;

    if (t < NCAND) spos[t] = g_cp[b * NCAND + t];
    __syncthreads();

    // ---- stage all 10 patches, candidate-interleaved: dsm[ic*90 + p*10 + cand]
    for (int i = 0; i < 90; ++i) {
        int e = t + i * 256;
        int cand = e % 10;
        int q = e / 10;
        int ic = q / 9, p = q - ic * 9;
        int pos = spos[cand];
        int rr = pos / 38 - 1 + p / 3, cc = pos % 38 - 1 + p % 3;
        dsm[ic * 90 + p * 10 + cand] = (rr >= 0 && rr < 38 && cc >= 0 && cc < 38)
               ? in[((size_t)(b * ICH + ic) * 38 + rr) * 38 + cc] : 0.f;
    }
    __syncthreads();

    // ---- exact conv1 partials, 5 candidate-pairs via f32x2 ----
    ull xa2[5][4];
    #pragma unroll
    for (int cp = 0; cp < 5; ++cp)
        #pragma unroll
        for (int j = 0; j < 4; ++j) xa2[cp][j] = 0ull;

    const float4* wr = (const float4*)(W1 + oc * 1024) + half * 128;
    const float* spb = dsm + half * 128 * 90;
    for (int icl = 0; icl < 128; ++icl) {
        float4 w = wr[icl];
        ull wx, wy, wz, ww;
        PACK2(wx, w.x); PACK2(wy, w.y); PACK2(wz, w.z); PACK2(ww, w.w);
        const ull* row = (const ull*)(spb + icl * 90);
        #pragma unroll
        for (int cp = 0; cp < 5; ++cp) {
            ull s0 = row[cp],      s1 = row[5 + cp],  s2 = row[10 + cp];
            ull s3 = row[15 + cp], s4 = row[20 + cp], s5 = row[25 + cp];
            ull s6 = row[30 + cp], s7 = row[35 + cp], s8 = row[40 + cp];
            FMA2(xa2[cp][0], wx, s0); FMA2(xa2[cp][0], wy, s1);
            FMA2(xa2[cp][0], wz, s3); FMA2(xa2[cp][0], ww, s4);
            FMA2(xa2[cp][1], wx, s1); FMA2(xa2[cp][1], wy, s2);
            FMA2(xa2[cp][1], wz, s4); FMA2(xa2[cp][1], ww, s5);
            FMA2(xa2[cp][2], wx, s3); FMA2(xa2[cp][2], wy, s4);
            FMA2(xa2[cp][2], wz, s6); FMA2(xa2[cp][2], ww, s7);
            FMA2(xa2[cp][3], wx, s4); FMA2(xa2[cp][3], wy, s5);
            FMA2(xa2[cp][3], wz, s7); FMA2(xa2[cp][3], ww, s8);
        }
    }
    __syncthreads();   // done reading spatch; reuse dsm

    float* sxa10 = dsm;                 // [10][128][4]
    float* red10 = dsm + NCAND * 512;   // [10][4][128]
    if (half == 0) {
        #pragma unroll
        for (int cp = 0; cp < 5; ++cp)
            #pragma unroll
            for (int j = 0; j < 4; ++j) {
                float lo, hi;
                UNPACK2(lo, hi, xa2[cp][j]);
                sxa10[(2 * cp)     * 512 + oc * 4 + j] = lo;
                sxa10[(2 * cp + 1) * 512 + oc * 4 + j] = hi;
            }
    }
    __syncthreads();
    if (half == 1) {
        #pragma unroll
        for (int cp = 0; cp < 5; ++cp)
            #pragma unroll
            for (int j = 0; j < 4; ++j) {
                float lo, hi;
                UNPACK2(lo, hi, xa2[cp][j]);
                sxa10[(2 * cp)     * 512 + oc * 4 + j] += lo;
                sxa10[(2 * cp + 1) * 512 + oc * 4 + j] += hi;
            }
    }
    __syncthreads();

    if (half == 0) {
        float wd[4][4];
        #pragma unroll
        for (int ch = 0; ch < 4; ++ch)
            #pragma unroll
            for (int tp = 0; tp < 4; ++tp)
                wd[ch][tp] = Wc[(ch + 4) * 512 + oc * 4 + tp]
                           - Wc[ch * 512 + oc * 4 + tp];
        float bv1 = b1[oc];
        #pragma unroll
        for (int c = 0; c < NCAND; ++c) {
            float x0 = fmaxf(sxa10[c * 512 + oc * 4 + 0] + bv1, 0.f);
            float x1 = fmaxf(sxa10[c * 512 + oc * 4 + 1] + bv1, 0.f);
            float x2 = fmaxf(sxa10[c * 512 + oc * 4 + 2] + bv1, 0.f);
            float x3 = fmaxf(sxa10[c * 512 + oc * 4 + 3] + bv1, 0.f);
            #pragma unroll
            for (int ch = 0; ch < 4; ++ch)
                red10[c * 512 + ch * 128 + oc] =
                    wd[ch][0] * x0 + wd[ch][1] * x1 + wd[ch][2] * x2 + wd[ch][3] * x3;
        }
    }
    __syncthreads();
    if (t < NCAND * 4) {
        int c = t >> 2, ch = t & 3;
        float s = 0.f;
        #pragma unroll 8
        for (int k = 0; k < 128; ++k) s += red10[c * 512 + ch * 128 + k];
        ssc[t] = s + bc[ch + 4] - bc[ch];
    }
    __syncthreads();
    if (t == 0) {
        float bv = -1e30f; int bf = 0x7fffffff;
        for (int c = 0; c < NCAND; ++c) {
            int pos = spos[c];
            #pragma unroll
            for (int ch = 0; ch < 4; ++ch) {
                float v = ssc[c * 4 + ch];
                int f = ch * KPOS + pos;
                if (v > bv || (v == bv && f < bf)) { bv = v; bf = f; }
            }
        }
        sBestV = bv; sBestF = bf;
    }
    __syncthreads();

    // ---- exact x at decoded proposal position kp = f>>2, then box ----
    const int f = sBestF;
    const int kp = f >> 2, ap = f & 3;
    const int hp = kp / 38, wp = kp % 38;
    #pragma unroll
    for (int i = 0; i < 9; ++i) {
        int e = t + i * 256;
        if (e < 2304) {
            int ic = e / 9, p = e - ic * 9;
            int rr = hp - 1 + p / 3, cc = wp - 1 + p % 3;
            dsm[e] = (rr >= 0 && rr < 38 && cc >= 0 && cc < 38)
                   ? in[((size_t)(b * ICH + ic) * 38 + rr) * 38 + cc] : 0.f;
        }
    }
    __syncthreads();
    float xw[4] = {0.f, 0.f, 0.f, 0.f};
    for (int icl = 0; icl < 128; ++icl) {
        float4 w = wr[icl];
        int ic = half * 128 + icl;
        const float* sf = &dsm[ic * 9];
        float s0 = sf[0], s1 = sf[1], s2 = sf[2];
        float s3 = sf[3], s4 = sf[4], s5 = sf[5];
        float s6 = sf[6], s7 = sf[7], s8 = sf[8];
        xw[0] += w.x * s0 + w.y * s1 + w.z * s3 + w.w * s4;
        xw[1] += w.x * s1 + w.y * s2 + w.z * s4 + w.w * s5;
        xw[2] += w.x * s3 + w.y * s4 + w.z * s6 + w.w * s7;
        xw[3] += w.x * s4 + w.y * s5 + w.z * s7 + w.w * s8;
    }
    if (half == 0)
        #pragma unroll
        for (int j = 0; j < 4; ++j) sxa[oc * 4 + j] = xw[j];
    __syncthreads();
    if (half == 1)
        #pragma unroll
        for (int j = 0; j < 4; ++j) sxa[oc * 4 + j] += xw[j];
    __syncthreads();

    if (half == 0) {
        float bv1 = b1[oc];
        float x0 = fmaxf(sxa[oc * 4 + 0] + bv1, 0.f);
        float x1 = fmaxf(sxa[oc * 4 + 1] + bv1, 0.f);
        float x2 = fmaxf(sxa[oc * 4 + 2] + bv1, 0.f);
        float x3 = fmaxf(sxa[oc * 4 + 3] + bv1, 0.f);
        #pragma unroll
        for (int j = 0; j < 4; ++j) {
            const float* wq = Wb + (ap * 4 + j) * 512 + oc * 4;
            sred[j][oc] = x0 * wq[0] + x1 * wq[1] + x2 * wq[2] + x3 * wq[3];
        }
    }
    __syncthreads();
    if (t < 4) {
        float s = 0.f;
        #pragma unroll 8
        for (int k = 0; k < 128; ++k) s += sred[t][k];
        s += bb[ap * 4 + t];
        float shift = (t & 1) ? hp * 16.f : wp * 16.f;
        float scv = im_info[0];
        float box = (anchors[ap * 4 + t] + shift + s) * scv;
        out[b * 9 + t]     = truncf(box / scv);
        out[b * 9 + 4 + t] = box;
    }
    if (t == 4) out[b * 9 + 8] = 1.f / (1.f + expf(-sBestV));
}

// ---------------------------------------------------------------------------
// K4: proposal loss.
// ---------------------------------------------------------------------------
__global__ void loss_kernel(const float* __restrict__ gt,
                            const int* __restrict__ central,
                            float* __restrict__ out, int out_size)
{
    int idx = central[0];
    bool valid = idx < BATCH;
    int ix = idx < 0 ? 0 : (idx > BATCH - 1 ? BATCH - 1 : idx);
    float vb0 = out[ix * 9 + 4], vb1 = out[ix * 9 + 5];
    float vb2 = out[ix * 9 + 6], vb3 = out[ix * 9 + 7];
    float vs  = out[ix * 9 + 8];
    float xi1 = fmaxf(gt[0], vb0);
    float yi1 = fmaxf(gt[1], vb1);
    float xi2 = fmaxf(gt[2], vb2);
    float yi2 = fmaxf(gt[3], vb3);
    float inter = (xi2 - xi1) * (yi2 - yi1);
    float a1 = (gt[2] - gt[0]) * (gt[3] - gt[1]);
    float a2 = (vb2 - vb0) * (vb3 - vb1);
    float iou = inter / (a1 + a2 - inter);
    float lv = (iou > 0.7f) ? -logf(vs + 1e-5f) : -logf(1.f - vs + 1e-5f);
    out[out_size - 1] = valid ? lv : 0.f;
}

// ---------------------------------------------------------------------------
extern "C" void kernel_launch(void* const* d_in, const int* in_sizes, int n_in,
                              void* d_out, int out_size)
{
    const float* base_feat = (const float*)d_in[0];
    const int*   central   = (const int*)  d_in[1];
    const float* im_info   = (const float*)d_in[2];
    const float* gt_boxes  = (const float*)d_in[3];
    const float* W1        = (const float*)d_in[4];
    const float* b1        = (const float*)d_in[5];
    const float* Wc        = (const float*)d_in[6];
    const float* bc        = (const float*)d_in[7];
    const float* Wb        = (const float*)d_in[8];
    const float* bb        = (const float*)d_in[9];
    const float* anchors   = (const float*)d_in[10];
    float* out = (float*)d_out;

    cudaFuncSetAttribute(conv1_tc_kernel,
                         cudaFuncAttributeMaxDynamicSharedMemorySize, SMEM_TC);
    cudaFuncSetAttribute(cls_topk_kernel,
                         cudaFuncAttributeMaxDynamicSharedMemorySize, K2_SMEM);
    cudaFuncSetAttribute(box_kernel,
                         cudaFuncAttributeMaxDynamicSharedMemorySize, K3_SMEM);

    prep_w_kernel<<<256, 256>>>(W1);
    prep_in_kernel<<<dim3(19, 8, BATCH), 256>>>(base_feat);
    conv1_tc_kernel<<<BATCH * 13, 256, SMEM_TC>>>(b1);
    cls_topk_kernel<<<dim3(5, BATCH), 256, K2_SMEM>>>(Wc, bc);
    box_kernel<<<BATCH, 256, K3_SMEM>>>(base_feat, W1, b1, Wc, bc,
                                        Wb, bb, anchors, im_info, out);
    loss_kernel<<<1, 1>>>(gt_boxes, central, out, out_size);
}

// round 17
// speedup vs baseline: 1.5887x; 1.1401x over previous
#include <cuda_runtime.h>
#include <cuda_fp16.h>
#include <math.h>
#include <cstdint>

#define BATCH 300
#define ICH   256
#define OC1   128
#define KPOS  1444
#define ROWS40 1664
#define NCAND 10

typedef unsigned long long ull;

// ------------------- device scratch -------------------
__device__ int g_cp[BATCH * NCAND];            // candidate positions (top-2 x 5 tiles)
__device__ __align__(16) unsigned char g_Ah[16 * 16384];
__device__ __half g_pH[(size_t)BATCH * KPOS * ICH];
// per-row cls projections: [b][row40][16 = tap*4+ch], fp16
__device__ __align__(16) __half g_P[(size_t)BATCH * ROWS40 * 16];
// diff weights transposed for the P-GEMM: [16 n][128 oc] fp16
__device__ __align__(16) __half g_WD[16 * 128];

__device__ __forceinline__ uint32_t smem_u32(const void* p) {
    return (uint32_t)__cvta_generic_to_shared(p);
}
__device__ __forceinline__ void ldmx4(uint32_t* r, uint32_t addr) {
    asm volatile("ldmatrix.sync.aligned.m8n8.x4.shared.b16 {%0,%1,%2,%3}, [%4];"
        : "=r"(r[0]), "=r"(r[1]), "=r"(r[2]), "=r"(r[3]) : "r"(addr));
}
__device__ __forceinline__ void mma16816(float* d, const uint32_t* a, const uint32_t* b) {
    asm volatile("mma.sync.aligned.m16n8k16.row.col.f32.f16.f16.f32 "
        "{%0,%1,%2,%3},{%4,%5,%6,%7},{%8,%9},{%0,%1,%2,%3};"
        : "+f"(d[0]), "+f"(d[1]), "+f"(d[2]), "+f"(d[3])
        : "r"(a[0]), "r"(a[1]), "r"(a[2]), "r"(a[3]), "r"(b[0]), "r"(b[1]));
}
__device__ __forceinline__ void cpasync16z(uint32_t dst, const void* src, uint32_t sz) {
    asm volatile("cp.async.cg.shared.global [%0], [%1], 16, %2;"
        :: "r"(dst), "l"(src), "r"(sz));
}
__device__ __forceinline__ bool better(float v, int p, float w, int q) {
    return v > w || (v == w && p < q);
}

#define FMA2(acc, a, s) \
    asm("fma.rn.f32x2 %0, %1, %2, %0;" : "+l"(acc) : "l"(a), "l"(s))
#define PACK2(d, f) \
    asm("mov.b64 %0, {%1, %1};" : "=l"(d) : "f"(f))
#define UNPACK2(lo, hi, v) \
    asm("mov.b64 {%0, %1}, %2;" : "=f"(lo), "=f"(hi) : "l"(v))

// ---------------------------------------------------------------------------
// K0a: W1 -> fp16 hi image [c][oc][64k], k = tap*16 + icL.
// ---------------------------------------------------------------------------
__global__ __launch_bounds__(256) void prep_w_kernel(const float* __restrict__ W1) {
    int p = blockIdx.x * 256 + threadIdx.x;
    int oc = p >> 9;
    int kk = (p & 511) << 1;
    int c = kk >> 6, k2 = kk & 63;
    int tap = k2 >> 4, icL = k2 & 15;
    __half h0 = __float2half(W1[oc * 1024 + (c * 16 + icL) * 4 + tap]);
    __half h1 = __float2half(W1[oc * 1024 + (c * 16 + icL + 1) * 4 + tap]);
    uint32_t uh = ((uint32_t)__half_as_ushort(h1) << 16) | __half_as_ushort(h0);
    *(uint32_t*)(g_Ah + (uint32_t)(c * 16384 + oc * 128 + k2 * 2)) = uh;
}

// K0c: diff weights wd^T [16][128] fp16 for the fused P-GEMM.
__global__ __launch_bounds__(256) void prep_wd_kernel(const float* __restrict__ Wc) {
    int e = blockIdx.x * 256 + threadIdx.x;        // 0..2047
    int row = e >> 7, oc = e & 127;
    int tap = row >> 2, ch = row & 3;
    float d = Wc[(ch + 4) * 512 + oc * 4 + tap] - Wc[ch * 512 + oc * 4 + tap];
    g_WD[row * 128 + oc] = __float2half(d);
}

// ---------------------------------------------------------------------------
// K0b: transpose input: [b][ic][1444] fp32 -> [b][pos][ic] fp16.
// ---------------------------------------------------------------------------
__global__ __launch_bounds__(256) void prep_in_kernel(const float* __restrict__ in) {
    __shared__ float st[32][77];
    const int pt = blockIdx.x, icb = blockIdx.y, b = blockIdx.z;
    const int t = threadIdx.x;
    const float* src = in + ((size_t)(b * ICH + icb * 32) * KPOS) + pt * 76;
    #pragma unroll
    for (int i = 0; i < 10; ++i) {
        int e = t + i * 256;
        if (e < 2432) {
            int icL = e / 76, s = e - icL * 76;
            st[icL][s] = src[(size_t)icL * KPOS + s];
        }
    }
    __syncthreads();
    #pragma unroll
    for (int i = 0; i < 10; ++i) {
        int e = t + i * 256;
        if (e < 2432) {
            int posL = e >> 5, icL = e & 31;
            size_t d = (size_t)(b * KPOS + pt * 76 + posL) * ICH + icb * 32 + icL;
            g_pH[d] = __float2half(st[icL][posL]);
        }
    }
}

// ---------------------------------------------------------------------------
// K1: conv1, tap-decomposed 1-pass fp16 + FUSED P-GEMM epilogue.
// Writes only g_P[b][row40][16] (no full x output).
// ---------------------------------------------------------------------------
#define APITCH 144
#define BPITCH 48
#define OFF_B  18432
#define BUFSZ  35328
#define OFF_WD (3 * BUFSZ)
#define SMEM_TC (3 * BUFSZ + 16 * 272)
#define TPITCH 136      /* halves; 272B row pitch */

__global__ __launch_bounds__(256, 2) void conv1_tc_kernel(
    const float* __restrict__ bias)
{
    extern __shared__ __align__(16) unsigned char sm[];
    const uint32_t smb = smem_u32(sm);
    const int t = threadIdx.x;
    const int b = blockIdx.x / 13;
    const int tile = blockIdx.x - b * 13;
    const int nbase = tile * 128;

    const int wid = t >> 5, l = t & 31;
    const int wm = wid & 3, wn = wid >> 2;
    const uint32_t aoff = (uint32_t)((wm * 32 + (l & 15)) * APITCH + ((l >> 4) & 1) * 16);
    const uint32_t boff = (uint32_t)((wn * 64 + (l & 7) + ((l >> 4) & 1) * 8) * BPITCH
                                     + ((l >> 3) & 1) * 16);

    // stage wd^T into smem (used only in epilogue; ordered by later syncs)
    {
        uint4 v = ((const uint4*)g_WD)[t];
        *(uint4*)(sm + OFF_WD + (t >> 4) * 272 + (t & 15) * 16) = v;
    }

    // ---- hoisted copy descriptors ----
    const uint32_t adst0 = (uint32_t)((t >> 3) * APITCH + (t & 7) * 16);
    const unsigned char* asrc0 = g_Ah + t * 16;
    const unsigned char* bsrc0;
    const unsigned char* bsrc1 = nullptr;
    uint32_t bdst0, bdst1 = 0, bsz0, bsz1 = 0;
    {
        int e = t;
        int s = e >> 1, half = e & 1;
        int m = nbase - 40 + s;
        int iy = m / 40, px = m - iy * 40;
        bool valid = (m >= 0) && (iy < 38) && (px >= 1) && (px <= 38);
        size_t si = valid ? ((size_t)(b * KPOS + iy * 38 + px - 1) * ICH + half * 8) : 0;
        bsrc0 = (const unsigned char*)(g_pH + si);
        bdst0 = (uint32_t)(OFF_B + s * BPITCH + half * 16);
        bsz0 = valid ? 16u : 0u;
    }
    if (t < 96) {
        int e = t + 256;
        int s = e >> 1, half = e & 1;
        int m = nbase - 40 + s;
        int iy = m / 40, px = m - iy * 40;
        bool valid = (m >= 0) && (iy < 38) && (px >= 1) && (px <= 38);
        size_t si = valid ? ((size_t)(b * KPOS + iy * 38 + px - 1) * ICH + half * 8) : 0;
        bsrc1 = (const unsigned char*)(g_pH + si);
        bdst1 = (uint32_t)(OFF_B + s * BPITCH + half * 16);
        bsz1 = valid ? 16u : 0u;
    }

    float acc[2][8][4];
    #pragma unroll
    for (int mt = 0; mt < 2; ++mt)
        #pragma unroll
        for (int nf = 0; nf < 8; ++nf)
            #pragma unroll
            for (int r = 0; r < 4; ++r) acc[mt][nf][r] = 0.f;

    auto issue = [&](int c) {
        const uint32_t bb = smb + (c % 3) * BUFSZ;
        const unsigned char* as = asrc0 + c * 16384;
        cpasync16z(bb + adst0,                 as,         16);
        cpasync16z(bb + adst0 + 32 * APITCH,   as + 4096,  16);
        cpasync16z(bb + adst0 + 64 * APITCH,   as + 8192,  16);
        cpasync16z(bb + adst0 + 96 * APITCH,   as + 12288, 16);
        cpasync16z(bb + bdst0, bsrc0 + c * 32, bsz0);
        if (t < 96) cpasync16z(bb + bdst1, bsrc1 + c * 32, bsz1);
        asm volatile("cp.async.commit_group;" ::: "memory");
    };

    auto compute = [&](int c) {
        const uint32_t bb = smb + (c % 3) * BUFSZ;
        #pragma unroll
        for (int tap = 0; tap < 4; ++tap) {
            const uint32_t koff = tap * 32;
            const int dlt = (tap >> 1) * 40 + (tap & 1);
            uint32_t Ah[2][4], Bh[8][2];
            ldmx4(Ah[0], bb + aoff + koff);
            ldmx4(Ah[1], bb + aoff + 16 * APITCH + koff);
            #pragma unroll
            for (int g = 0; g < 4; ++g) {
                uint32_t r[4];
                ldmx4(r, bb + OFF_B + boff + (dlt + g * 16) * BPITCH);
                Bh[2*g][0] = r[0]; Bh[2*g][1] = r[1];
                Bh[2*g+1][0] = r[2]; Bh[2*g+1][1] = r[3];
            }
            #pragma unroll
            for (int mt = 0; mt < 2; ++mt)
                #pragma unroll
                for (int nf = 0; nf < 8; ++nf)
                    mma16816(acc[mt][nf], Ah[mt], Bh[nf]);
        }
    };

    issue(0);
    issue(1);
    for (int c = 0; c < 16; ++c) {
        if (c == 15) {
            asm volatile("cp.async.wait_group 0;" ::: "memory");
        } else {
            asm volatile("cp.async.wait_group 1;" ::: "memory");
        }
        __syncthreads();
        if (c < 14) issue(c + 2);
        compute(c);
    }
    __syncthreads();

    // ---- epilogue: bias+relu -> fp16 sT [128 pos][TPITCH] ----
    __half* sT = (__half*)sm;
    float bia[2][2];
    #pragma unroll
    for (int mt = 0; mt < 2; ++mt) {
        int mb = wm * 32 + mt * 16 + (l >> 2);
        bia[mt][0] = __ldg(bias + mb);
        bia[mt][1] = __ldg(bias + mb + 8);
    }
    #pragma unroll
    for (int mt = 0; mt < 2; ++mt)
        #pragma unroll
        for (int nf = 0; nf < 8; ++nf)
            #pragma unroll
            for (int r = 0; r < 4; ++r) {
                int m = wm * 32 + mt * 16 + (l >> 2) + ((r >> 1) ? 8 : 0);
                int n = wn * 64 + nf * 8 + 2 * (l & 3) + (r & 1);
                float v = acc[mt][nf][r] + bia[mt][r >> 1];
                v = v > 0.f ? v : 0.f;
                sT[n * TPITCH + m] = __float2half(v);
            }
    __syncthreads();

    // ---- fused P-GEMM: P[pos][16] = sT(pos x oc) @ wd^T(oc x 16) ----
    {
        float cP[2][4];
        #pragma unroll
        for (int nf = 0; nf < 2; ++nf)
            #pragma unroll
            for (int r = 0; r < 4; ++r) cP[nf][r] = 0.f;
        const uint32_t apoff = smb + (uint32_t)((wid * 16 + (l & 15)) * 272
                                                + ((l >> 4) & 1) * 16);
        const uint32_t bpoff = smb + OFF_WD
            + (uint32_t)(((l & 7) + ((l >> 4) & 1) * 8) * 272 + ((l >> 3) & 1) * 16);
        #pragma unroll
        for (int ks = 0; ks < 8; ++ks) {
            uint32_t Ar[4], Br[4];
            ldmx4(Ar, apoff + ks * 32);
            ldmx4(Br, bpoff + ks * 32);
            uint32_t B0[2] = {Br[0], Br[1]};
            uint32_t B1[2] = {Br[2], Br[3]};
            mma16816(cP[0], Ar, B0);
            mma16816(cP[1], Ar, B1);
        }
        int rowl = l >> 2, col0 = 2 * (l & 3);
        __half* gp = g_P + ((size_t)b * ROWS40 + nbase + wid * 16) * 16;
        #pragma unroll
        for (int nf = 0; nf < 2; ++nf) {
            *(__half2*)(gp + rowl * 16 + nf * 8 + col0) =
                __floats2half2_rn(cP[nf][0], cP[nf][1]);
            *(__half2*)(gp + (rowl + 8) * 16 + nf * 8 + col0) =
                __floats2half2_rn(cP[nf][2], cP[nf][3]);
        }
    }
}

// ---------------------------------------------------------------------------
// K2: tiny — sum 4 P entries per (pos,ch), channel-max, top-2 per 8-row tile.
// grid (5 tiles, 300 batches), 256 threads.
// ---------------------------------------------------------------------------
__global__ __launch_bounds__(256) void cls_topk_kernel(
    const float* __restrict__ bc)
{
    __shared__ __align__(16) __half sP[360 * 16];
    __shared__ float rv1[256], rv2[256];
    __shared__ int   rp1[256], rp2[256];
    const int tb = blockIdx.x, b = blockIdx.y, t = threadIdx.x;
    const int y0 = tb * 8;
    const int nrows = (38 - y0 < 8) ? 38 - y0 : 8;
    const int npos = nrows * 38;
    const int base40 = y0 * 40;

    // load 360 P rows (11.5 KB)
    const uint4* gp = (const uint4*)(g_P + ((size_t)b * ROWS40 + base40) * 16);
    #pragma unroll
    for (int i = 0; i < 3; ++i) {
        int e = t + i * 256;
        if (e < 720) ((uint4*)sP)[e] = gp[e];
    }
    __syncthreads();

    float bd[4];
    #pragma unroll
    for (int a = 0; a < 4; ++a) bd[a] = bc[a + 4] - bc[a];

    float v1 = -1e30f, v2 = -1e30f;
    int p1 = 0x7fffffff, p2 = 0x7fffffff;
    #pragma unroll
    for (int it = 0; it < 2; ++it) {
        int pl = t + it * 256;
        if (pl < npos) {
            int iy = pl / 38, ix = pl - iy * 38;
            int rl = iy * 40 + ix;
            const __half* p0 = sP + rl * 16;
            float pv = -1e30f;
            #pragma unroll
            for (int ch = 0; ch < 4; ++ch) {
                float v = __half2float(p0[ch])
                        + __half2float(p0[16 + 4 + ch])
                        + __half2float(p0[640 + 8 + ch])
                        + __half2float(p0[656 + 12 + ch])
                        + bd[ch];
                if (v > pv) pv = v;
            }
            int p = (y0 + iy) * 38 + ix;
            if (better(pv, p, v1, p1)) { v2 = v1; p2 = p1; v1 = pv; p1 = p; }
            else if (better(pv, p, v2, p2)) { v2 = pv; p2 = p; }
        }
    }
    rv1[t] = v1; rp1[t] = p1; rv2[t] = v2; rp2[t] = p2;
    __syncthreads();
    for (int s = 128; s > 0; s >>= 1) {
        if (t < s) {
            float a1 = rv1[t], a2 = rv2[t];
            int   e1 = rp1[t], e2 = rp2[t];
            float w1 = rv1[t + s], w2 = rv2[t + s];
            int   q1 = rp1[t + s], q2 = rp2[t + s];
            float n1, n2; int m1, m2;
            if (better(a1, e1, w1, q1)) {
                n1 = a1; m1 = e1;
                if (better(w1, q1, a2, e2)) { n2 = w1; m2 = q1; }
                else                        { n2 = a2; m2 = e2; }
            } else {
                n1 = w1; m1 = q1;
                if (better(a1, e1, w2, q2)) { n2 = a1; m2 = e1; }
                else                        { n2 = w2; m2 = q2; }
            }
            rv1[t] = n1; rp1[t] = m1; rv2[t] = n2; rp2[t] = m2;
        }
        __syncthreads();
    }
    if (t == 0) {
        g_cp[b * NCAND + tb * 2]     = rp1[0];
        g_cp[b * NCAND + tb * 2 + 1] = rp2[0];
    }
}

// ---------------------------------------------------------------------------
// K3: fused exact re-score of all 10 candidates (f32x2) + exact winner box.
// (frozen from R16)
// ---------------------------------------------------------------------------
#define K3_SMEM (NCAND * 2304 * 4)

__global__ __launch_bounds__(256) void box_kernel(
    const float* __restrict__ in, const float* __restrict__ W1,
    const float* __restrict__ b1,
    const float* __restrict__ Wc, const float* __restrict__ bc,
    const float* __restrict__ Wb, const float* __restrict__ bb,
    const float* __restrict__ anchors, const float* __restrict__ im_info,
    float* __restrict__ out)
{
    extern __shared__ float dsm[];
    __shared__ int   spos[NCAND];
    __shared__ float ssc[NCAND * 4];
    __shared__ float sxa[512];
    __shared__ float sred[4][128];
    __shared__ float sBestV;
    __shared__ int   sBestF;

    const int b = blockIdx.x, t = threadIdx.x;
    const int half = t >> 7, oc = t & 127;

    if (t < NCAND) spos[t] = g_cp[b * NCAND + t];
    __syncthreads();

    for (int i = 0; i < 90; ++i) {
        int e = t + i * 256;
        int cand = e % 10;
        int q = e / 10;
        int ic = q / 9, p = q - ic * 9;
        int pos = spos[cand];
        int rr = pos / 38 - 1 + p / 3, cc = pos % 38 - 1 + p % 3;
        dsm[ic * 90 + p * 10 + cand] = (rr >= 0 && rr < 38 && cc >= 0 && cc < 38)
               ? in[((size_t)(b * ICH + ic) * 38 + rr) * 38 + cc] : 0.f;
    }
    __syncthreads();

    ull xa2[5][4];
    #pragma unroll
    for (int cp = 0; cp < 5; ++cp)
        #pragma unroll
        for (int j = 0; j < 4; ++j) xa2[cp][j] = 0ull;

    const float4* wr = (const float4*)(W1 + oc * 1024) + half * 128;
    const float* spb = dsm + half * 128 * 90;
    for (int icl = 0; icl < 128; ++icl) {
        float4 w = wr[icl];
        ull wx, wy, wz, ww;
        PACK2(wx, w.x); PACK2(wy, w.y); PACK2(wz, w.z); PACK2(ww, w.w);
        const ull* row = (const ull*)(spb + icl * 90);
        #pragma unroll
        for (int cp = 0; cp < 5; ++cp) {
            ull s0 = row[cp],      s1 = row[5 + cp],  s2 = row[10 + cp];
            ull s3 = row[15 + cp], s4 = row[20 + cp], s5 = row[25 + cp];
            ull s6 = row[30 + cp], s7 = row[35 + cp], s8 = row[40 + cp];
            FMA2(xa2[cp][0], wx, s0); FMA2(xa2[cp][0], wy, s1);
            FMA2(xa2[cp][0], wz, s3); FMA2(xa2[cp][0], ww, s4);
            FMA2(xa2[cp][1], wx, s1); FMA2(xa2[cp][1], wy, s2);
            FMA2(xa2[cp][1], wz, s4); FMA2(xa2[cp][1], ww, s5);
            FMA2(xa2[cp][2], wx, s3); FMA2(xa2[cp][2], wy, s4);
            FMA2(xa2[cp][2], wz, s6); FMA2(xa2[cp][2], ww, s7);
            FMA2(xa2[cp][3], wx, s4); FMA2(xa2[cp][3], wy, s5);
            FMA2(xa2[cp][3], wz, s7); FMA2(xa2[cp][3], ww, s8);
        }
    }
    __syncthreads();

    float* sxa10 = dsm;
    float* red10 = dsm + NCAND * 512;
    if (half == 0) {
        #pragma unroll
        for (int cp = 0; cp < 5; ++cp)
            #pragma unroll
            for (int j = 0; j < 4; ++j) {
                float lo, hi;
                UNPACK2(lo, hi, xa2[cp][j]);
                sxa10[(2 * cp)     * 512 + oc * 4 + j] = lo;
                sxa10[(2 * cp + 1) * 512 + oc * 4 + j] = hi;
            }
    }
    __syncthreads();
    if (half == 1) {
        #pragma unroll
        for (int cp = 0; cp < 5; ++cp)
            #pragma unroll
            for (int j = 0; j < 4; ++j) {
                float lo, hi;
                UNPACK2(lo, hi, xa2[cp][j]);
                sxa10[(2 * cp)     * 512 + oc * 4 + j] += lo;
                sxa10[(2 * cp + 1) * 512 + oc * 4 + j] += hi;
            }
    }
    __syncthreads();

    if (half == 0) {
        float wd[4][4];
        #pragma unroll
        for (int ch = 0; ch < 4; ++ch)
            #pragma unroll
            for (int tp = 0; tp < 4; ++tp)
                wd[ch][tp] = Wc[(ch + 4) * 512 + oc * 4 + tp]
                           - Wc[ch * 512 + oc * 4 + tp];
        float bv1 = b1[oc];
        #pragma unroll
        for (int c = 0; c < NCAND; ++c) {
            float x0 = fmaxf(sxa10[c * 512 + oc * 4 + 0] + bv1, 0.f);
            float x1 = fmaxf(sxa10[c * 512 + oc * 4 + 1] + bv1, 0.f);
            float x2 = fmaxf(sxa10[c * 512 + oc * 4 + 2] + bv1, 0.f);
            float x3 = fmaxf(sxa10[c * 512 + oc * 4 + 3] + bv1, 0.f);
            #pragma unroll
            for (int ch = 0; ch < 4; ++ch)
                red10[c * 512 + ch * 128 + oc] =
                    wd[ch][0] * x0 + wd[ch][1] * x1 + wd[ch][2] * x2 + wd[ch][3] * x3;
        }
    }
    __syncthreads();
    if (t < NCAND * 4) {
        int c = t >> 2, ch = t & 3;
        float s = 0.f;
        #pragma unroll 8
        for (int k = 0; k < 128; ++k) s += red10[c * 512 + ch * 128 + k];
        ssc[t] = s + bc[ch + 4] - bc[ch];
    }
    __syncthreads();
    if (t == 0) {
        float bv = -1e30f; int bf = 0x7fffffff;
        for (int c = 0; c < NCAND; ++c) {
            int pos = spos[c];
            #pragma unroll
            for (int ch = 0; ch < 4; ++ch) {
                float v = ssc[c * 4 + ch];
                int f = ch * KPOS + pos;
                if (v > bv || (v == bv && f < bf)) { bv = v; bf = f; }
            }
        }
        sBestV = bv; sBestF = bf;
    }
    __syncthreads();

    const int f = sBestF;
    const int kp = f >> 2, ap = f & 3;
    const int hp = kp / 38, wp = kp % 38;
    #pragma unroll
    for (int i = 0; i < 9; ++i) {
        int e = t + i * 256;
        if (e < 2304) {
            int ic = e / 9, p = e - ic * 9;
            int rr = hp - 1 + p / 3, cc = wp - 1 + p % 3;
            dsm[e] = (rr >= 0 && rr < 38 && cc >= 0 && cc < 38)
                   ? in[((size_t)(b * ICH + ic) * 38 + rr) * 38 + cc] : 0.f;
        }
    }
    __syncthreads();
    float xw[4] = {0.f, 0.f, 0.f, 0.f};
    for (int icl = 0; icl < 128; ++icl) {
        float4 w = wr[icl];
        int ic = half * 128 + icl;
        const float* sf = &dsm[ic * 9];
        float s0 = sf[0], s1 = sf[1], s2 = sf[2];
        float s3 = sf[3], s4 = sf[4], s5 = sf[5];
        float s6 = sf[6], s7 = sf[7], s8 = sf[8];
        xw[0] += w.x * s0 + w.y * s1 + w.z * s3 + w.w * s4;
        xw[1] += w.x * s1 + w.y * s2 + w.z * s4 + w.w * s5;
        xw[2] += w.x * s3 + w.y * s4 + w.z * s6 + w.w * s7;
        xw[3] += w.x * s4 + w.y * s5 + w.z * s7 + w.w * s8;
    }
    if (half == 0)
        #pragma unroll
        for (int j = 0; j < 4; ++j) sxa[oc * 4 + j] = xw[j];
    __syncthreads();
    if (half == 1)
        #pragma unroll
        for (int j = 0; j < 4; ++j) sxa[oc * 4 + j] += xw[j];
    __syncthreads();

    if (half == 0) {
        float bv1 = b1[oc];
        float x0 = fmaxf(sxa[oc * 4 + 0] + bv1, 0.f);
        float x1 = fmaxf(sxa[oc * 4 + 1] + bv1, 0.f);
        float x2 = fmaxf(sxa[oc * 4 + 2] + bv1, 0.f);
        float x3 = fmaxf(sxa[oc * 4 + 3] + bv1, 0.f);
        #pragma unroll
        for (int j = 0; j < 4; ++j) {
            const float* wq = Wb + (ap * 4 + j) * 512 + oc * 4;
            sred[j][oc] = x0 * wq[0] + x1 * wq[1] + x2 * wq[2] + x3 * wq[3];
        }
    }
    __syncthreads();
    if (t < 4) {
        float s = 0.f;
        #pragma unroll 8
        for (int k = 0; k < 128; ++k) s += sred[t][k];
        s += bb[ap * 4 + t];
        float shift = (t & 1) ? hp * 16.f : wp * 16.f;
        float scv = im_info[0];
        float box = (anchors[ap * 4 + t] + shift + s) * scv;
        out[b * 9 + t]     = truncf(box / scv);
        out[b * 9 + 4 + t] = box;
    }
    if (t == 4) out[b * 9 + 8] = 1.f / (1.f + expf(-sBestV));
}

// ---------------------------------------------------------------------------
// K4: proposal loss.
// ---------------------------------------------------------------------------
__global__ void loss_kernel(const float* __restrict__ gt,
                            const int* __restrict__ central,
                            float* __restrict__ out, int out_size)
{
    int idx = central[0];
    bool valid = idx < BATCH;
    int ix = idx < 0 ? 0 : (idx > BATCH - 1 ? BATCH - 1 : idx);
    float vb0 = out[ix * 9 + 4], vb1 = out[ix * 9 + 5];
    float vb2 = out[ix * 9 + 6], vb3 = out[ix * 9 + 7];
    float vs  = out[ix * 9 + 8];
    float xi1 = fmaxf(gt[0], vb0);
    float yi1 = fmaxf(gt[1], vb1);
    float xi2 = fmaxf(gt[2], vb2);
    float yi2 = fmaxf(gt[3], vb3);
    float inter = (xi2 - xi1) * (yi2 - yi1);
    float a1 = (gt[2] - gt[0]) * (gt[3] - gt[1]);
    float a2 = (vb2 - vb0) * (vb3 - vb1);
    float iou = inter / (a1 + a2 - inter);
    float lv = (iou > 0.7f) ? -logf(vs + 1e-5f) : -logf(1.f - vs + 1e-5f);
    out[out_size - 1] = valid ? lv : 0.f;
}

// ---------------------------------------------------------------------------
extern "C" void kernel_launch(void* const* d_in, const int* in_sizes, int n_in,
                              void* d_out, int out_size)
{
    const float* base_feat = (const float*)d_in[0];
    const int*   central   = (const int*)  d_in[1];
    const float* im_info   = (const float*)d_in[2];
    const float* gt_boxes  = (const float*)d_in[3];
    const float* W1        = (const float*)d_in[4];
    const float* b1        = (const float*)d_in[5];
    const float* Wc        = (const float*)d_in[6];
    const float* bc        = (const float*)d_in[7];
    const float* Wb        = (const float*)d_in[8];
    const float* bb        = (const float*)d_in[9];
    const float* anchors   = (const float*)d_in[10];
    float* out = (float*)d_out;

    cudaFuncSetAttribute(conv1_tc_kernel,
                         cudaFuncAttributeMaxDynamicSharedMemorySize, SMEM_TC);
    cudaFuncSetAttribute(box_kernel,
                         cudaFuncAttributeMaxDynamicSharedMemorySize, K3_SMEM);

    prep_w_kernel<<<256, 256>>>(W1);
    prep_wd_kernel<<<8, 256>>>(Wc);
    prep_in_kernel<<<dim3(19, 8, BATCH), 256>>>(base_feat);
    conv1_tc_kernel<<<BATCH * 13, 256, SMEM_TC>>>(b1);
    cls_topk_kernel<<<dim3(5, BATCH), 256>>>(bc);
    box_kernel<<<BATCH, 256, K3_SMEM>>>(base_feat, W1, b1, Wc, bc,
                                        Wb, bb, anchors, im_info, out);
    loss_kernel<<<1, 1>>>(gt_boxes, central, out, out_size);
}